// round 8
// baseline (speedup 1.0000x reference)
#include <cuda_runtime.h>

// ============================================================================
// Expansion (e3nn): MUL_IN=128, IN_LS=0..4 (IN_DIM=3200), MUL_OUT=16,
// OUT_LS=0..3 (OUT_DIM=256), BATCH=2048.
// INSTR = [(i,j,k) : i in 0..4, j,k in 0..3, |j-k|<=i<=j+k]  (40 instrs,
// i-major order). Path weights: 32768 per instr, consecutive. Biases unused.
//
// out[b, u*(2j+1)+p + rowOff(j), v*(2k+1)+q + colOff(k)]
//   = sum_instr (1/128) * sum_{w,r} W[w,u,v] * w3j[p,q,r] * x_i[b,w,r]
//
// Plan:
//   init:   compute real Wigner-3j tables on device (fp64, exact reference
//           formula), normalized, into g_w3j.
//   phase1: per i-group GEMM  t[(b,r), uv] = x^T W / 128  into g_t.
//   phase2: per (b, (j,k)-block) CTA: out = sum_{i,r} w3j[pq,r] * t[r,uv],
//           with t and transposed w3j staged in smem.
// ============================================================================

#define DHC __host__ __device__ constexpr

DHC bool instr_valid(int i, int j, int k) {
    int d = j > k ? j - k : k - j;
    return d <= i && i <= j + k;
}
DHC int instr_id(int i, int j, int k) {
    int c = 0;
    for (int a = 0; a < 5; ++a)
        for (int b = 0; b < 4; ++b)
            for (int g = 0; g < 4; ++g)
                if (instr_valid(a, b, g)) {
                    if (a == i && b == j && g == k) return c;
                    ++c;
                }
    return -1;
}
// base offset (floats) of instr id's slab in g_t; slab = 2048*(2i+1)*256
DHC long long t_base_of(int id) {
    int c = 0; long long s = 0;
    for (int a = 0; a < 5; ++a)
        for (int b = 0; b < 4; ++b)
            for (int g = 0; g < 4; ++g)
                if (instr_valid(a, b, g)) {
                    if (c == id) return s * 524288LL;   // 2048*256
                    s += 2 * a + 1; ++c;
                }
    return 0;
}
// flat offset of instr id's w3j slab (layout per instr: [(p*Q+q)*R + r])
DHC int w3j_off_of(int id) {
    int c = 0, s = 0;
    for (int a = 0; a < 5; ++a)
        for (int b = 0; b < 4; ++b)
            for (int g = 0; g < 4; ++g)
                if (instr_valid(a, b, g)) {
                    if (c == id) return s;
                    s += (2 * b + 1) * (2 * g + 1) * (2 * a + 1); ++c;
                }
    return 0;
}
DHC int blk_off(int l) { return l == 0 ? 0 : l == 1 ? 16 : l == 2 ? 64 : 144; }
DHC int sum_L(int J, int K) {
    int s = 0;
    for (int i = 0; i < 5; ++i) if (instr_valid(i, J, K)) s += 2 * i + 1;
    return s;
}
DHC int xoff_of(int i) { int s = 0; for (int l = 0; l < i; ++l) s += 2 * l + 1; return 128 * s; }
DHC int ninstr_of(int i) {
    int c = 0;
    for (int b = 0; b < 4; ++b) for (int g = 0; g < 4; ++g) if (instr_valid(i, b, g)) ++c;
    return c;
}
DHC int group_first(int i) {
    for (int b = 0; b < 4; ++b) for (int g = 0; g < 4; ++g)
        if (instr_valid(i, b, g)) return instr_id(i, b, g);
    return 0;
}

// ---------------- device scratch (no runtime alloc allowed) ----------------
// sum over instrs of 2048*(2i+1)*256 = 524288 * 210
__device__ float g_t[110100480];
__device__ float g_w3j[5110];

// ============================================================================
// Wigner-3j init (fp64, replicates reference math verbatim)
// ============================================================================
struct cd { double re, im; };
__device__ __forceinline__ cd cmul(cd a, cd b) {
    cd r; r.re = a.re * b.re - a.im * b.im; r.im = a.re * b.im + a.im * b.re; return r;
}

__device__ const double g_fact[13] = {
    1.0, 1.0, 2.0, 6.0, 24.0, 120.0, 720.0, 5040.0, 40320.0, 362880.0,
    3628800.0, 39916800.0, 479001600.0
};

__device__ double su2cg(int j1, int m1, int j2, int m2, int j3, int m3) {
    // caller guarantees m3 == m1 + m2 and |m3| <= j3
    const double* F = g_fact;
    double C = sqrt((2.0 * j3 + 1.0) * F[j3 + j1 - j2] * F[j3 - j1 + j2] * F[j1 + j2 - j3]
                    * F[j3 + m3] * F[j3 - m3]
                    / (F[j1 + j2 + j3 + 1] * F[j1 - m1] * F[j1 + m1] * F[j2 - m2] * F[j2 + m2]));
    int vmin = -j1 + j2 + m3; if (-j1 + m1 > vmin) vmin = -j1 + m1; if (vmin < 0) vmin = 0;
    int vmax = j2 + j3 + m1;
    if (j3 - j1 + j2 < vmax) vmax = j3 - j1 + j2;
    if (j3 + m3 < vmax) vmax = j3 + m3;
    double S = 0.0;
    for (int v = vmin; v <= vmax; ++v) {
        double sgn = ((v + j2 + m2) & 1) ? -1.0 : 1.0;
        S += sgn * F[j2 + j3 + m1 - v] * F[j1 - m1 + v]
             / (F[v] * F[j3 - j1 + j2 - v] * F[j3 + m3 - v] * F[v + j1 - j2 - m3]);
    }
    return C * S;
}

// q[r][c] of _q_real_to_complex(l), including the (-i)^l global phase
__device__ cd q_ent(int l, int r, int c) {
    const double s = 0.70710678118654752440;
    int m = r - l;
    cd v; v.re = 0.0; v.im = 0.0;
    if (m < 0) {
        if (c == l - m)      { v.re = s; }
        else if (c == l + m) { v.im = -s; }
    } else if (m == 0) {
        if (c == l) v.re = 1.0;
    } else {
        double sg = (m & 1) ? -1.0 : 1.0;
        if (c == l + m)      { v.re = sg * s; }
        else if (c == l - m) { v.im = sg * s; }
    }
    int ph = l & 3;  // multiply by (-i)^l
    cd o = v;
    if (ph == 1)      { o.re = v.im;  o.im = -v.re; }
    else if (ph == 2) { o.re = -v.re; o.im = -v.im; }
    else if (ph == 3) { o.re = -v.im; o.im = v.re; }
    return o;
}

__global__ void wigner_init_kernel() {
    __shared__ double vals[1225];
    __shared__ double red[256];
    const int tid = threadIdx.x;
    const int id = blockIdx.x;
    int l1 = 0, l2 = 0, l3 = 0;
    {
        int c = 0;
        for (int a = 0; a < 5; ++a)
            for (int bb = 0; bb < 4; ++bb)
                for (int g = 0; g < 4; ++g)
                    if (instr_valid(a, bb, g)) {
                        if (c == id) { l3 = a; l1 = bb; l2 = g; }
                        ++c;
                    }
    }
    const int P = 2 * l1 + 1, Q2 = 2 * l2 + 1, R = 2 * l3 + 1;
    const int n = P * Q2 * R;
    double ss = 0.0;
    for (int e = tid; e < n; e += 256) {
        int jj = e / (Q2 * R);
        int rem = e - jj * (Q2 * R);
        int ll = rem / R;
        int mm = rem - ll * R;
        cd s; s.re = 0.0; s.im = 0.0;
        for (int i1 = 0; i1 < P; ++i1) {
            cd q1 = q_ent(l1, i1, jj);
            if (q1.re == 0.0 && q1.im == 0.0) continue;
            int m1 = i1 - l1;
            for (int k1 = 0; k1 < Q2; ++k1) {
                int m2 = k1 - l2;
                int m3 = m1 + m2;
                if (m3 < -l3 || m3 > l3) continue;
                cd q2 = q_ent(l2, k1, ll);
                if (q2.re == 0.0 && q2.im == 0.0) continue;
                cd q3 = q_ent(l3, l3 + m3, mm);
                if (q3.re == 0.0 && q3.im == 0.0) continue;
                double cg = su2cg(l1, m1, l2, m2, l3, m3);
                if (cg == 0.0) continue;
                cd q3c; q3c.re = q3.re; q3c.im = -q3.im;
                cd t = cmul(cmul(q1, q2), q3c);
                s.re += cg * t.re;
                s.im += cg * t.im;
            }
        }
        vals[e] = s.re;            // reference takes real part
        ss += s.re * s.re;
    }
    red[tid] = ss;
    __syncthreads();
    for (int st = 128; st > 0; st >>= 1) {
        if (tid < st) red[tid] += red[tid + st];
        __syncthreads();
    }
    const double inv = 1.0 / sqrt(red[0]);
    const int wo = w3j_off_of(id);
    for (int e = tid; e < n; e += 256)
        g_w3j[wo + e] = (float)(vals[e] * inv);
}

// ============================================================================
// Phase 1: per i-group GEMM.  t[(b*L+r), 256] = (1/128) x_i^T W
//   CTA tile 128(m) x 64(n), K=128 chunked by 32, 256 threads, 8x4 per thread.
// ============================================================================
template<int L>
__global__ void __launch_bounds__(256) phase1_kernel(
    const float* __restrict__ x, const float* __restrict__ wflat,
    int woff0, long long tb0, int xoff)
{
    __shared__ float As[32][132];   // [kk][m], pad 132 (16B-aligned rows)
    __shared__ float Bs[32][64];    // [kk][n]
    const int tid = threadIdx.x;
    const int m0 = blockIdx.x * 128;
    const int il = blockIdx.y >> 2;
    const int uv0 = (blockIdx.y & 3) * 64;
    const float* wB = wflat + woff0 + (size_t)il * 32768 + uv0;
    float* tC = g_t + tb0 + (long long)il * (2048LL * L * 256);
    const int ty = tid >> 4, tx = tid & 15;

    float acc[8][4];
#pragma unroll
    for (int u = 0; u < 8; ++u)
#pragma unroll
        for (int v = 0; v < 4; ++v) acc[u][v] = 0.0f;

    for (int k0 = 0; k0 < 128; k0 += 32) {
        // A: As[kk][ml] = x[b*3200 + xoff + (k0+kk)*L + r], m=m0+ml, b=m/L, r=m%L
#pragma unroll
        for (int it = 0; it < 16; ++it) {
            int e = tid + 256 * it;
            int kk = e & 31, ml = e >> 5;
            int m = m0 + ml;
            int b = m / L, r = m - b * L;
            As[kk][ml] = x[b * 3200 + xoff + (k0 + kk) * L + r];
        }
        // B: Bs[kk][nl] = w[(k0+kk)*256 + uv0 + nl]
#pragma unroll
        for (int it = 0; it < 8; ++it) {
            int e = tid + 256 * it;
            int nl = e & 63, kk = e >> 6;
            Bs[kk][nl] = wB[(k0 + kk) * 256 + nl];
        }
        __syncthreads();
#pragma unroll
        for (int kk = 0; kk < 32; ++kk) {
            float4 a0 = *(const float4*)(&As[kk][ty * 8]);
            float4 a1 = *(const float4*)(&As[kk][ty * 8 + 4]);
            float4 bv = *(const float4*)(&Bs[kk][tx * 4]);
            float a[8] = {a0.x, a0.y, a0.z, a0.w, a1.x, a1.y, a1.z, a1.w};
            float bb[4] = {bv.x, bv.y, bv.z, bv.w};
#pragma unroll
            for (int u = 0; u < 8; ++u)
#pragma unroll
                for (int v = 0; v < 4; ++v)
                    acc[u][v] = fmaf(a[u], bb[v], acc[u][v]);
        }
        __syncthreads();
    }
    // epilogue: scale by 1/128, store row-major [m][256]
#pragma unroll
    for (int u = 0; u < 8; ++u) {
        int m = m0 + ty * 8 + u;
        float4 o;
        o.x = acc[u][0] * 0.0078125f;
        o.y = acc[u][1] * 0.0078125f;
        o.z = acc[u][2] * 0.0078125f;
        o.w = acc[u][3] * 0.0078125f;
        *(float4*)(tC + (long long)m * 256 + uv0 + tx * 4) = o;
    }
}

// ============================================================================
// Phase 2: per (b, (J,K)-block) CTA.
//   out[pq, uv] = sum_kk ws[kk][pq] * ts[kk][uv],  kk = (instr-local i, r)
//   256 threads = 4 pq-sets x 64 uv4-lanes; NPQ pq rows per thread.
// ============================================================================
template<int J, int K>
__global__ void __launch_bounds__(256) phase2_kernel(float* __restrict__ out)
{
    constexpr int P = 2 * J + 1, Q = 2 * K + 1, PQ = P * Q;
    constexpr int SUML = sum_L(J, K);
    constexpr int NPQ = (PQ + 3) / 4;
    __shared__ float ts[SUML * 256];
    __shared__ float ws[SUML * PQ];
    const int tid = threadIdx.x;
    const int b = blockIdx.x;

    int kb = 0;
#pragma unroll
    for (int i = 0; i < 5; ++i) {
        if (!instr_valid(i, J, K)) continue;
        const int Ri = 2 * i + 1;
        const int id = instr_id(i, J, K);
        const long long tb = t_base_of(id) + (long long)b * (Ri * 256);
        const float4* src = (const float4*)(g_t + tb);
        float4* dst = (float4*)(ts + kb * 256);
        for (int idx = tid; idx < Ri * 64; idx += 256) dst[idx] = src[idx];
        const int wo = w3j_off_of(id);
        for (int idx = tid; idx < PQ * Ri; idx += 256) {
            int pq = idx / Ri, r = idx - pq * Ri;
            ws[(kb + r) * PQ + pq] = g_w3j[wo + idx];
        }
        kb += Ri;
    }
    __syncthreads();

    const int lane = tid & 63;   // uv4 lane: uv = lane*4 .. lane*4+3
    const int set = tid >> 6;    // pq set

    float acc[NPQ][4];
#pragma unroll
    for (int a = 0; a < NPQ; ++a)
#pragma unroll
        for (int c = 0; c < 4; ++c) acc[a][c] = 0.0f;

#pragma unroll
    for (int kk = 0; kk < SUML; ++kk) {
        float4 t4 = ((const float4*)ts)[kk * 64 + lane];
#pragma unroll
        for (int a = 0; a < NPQ; ++a) {
            int pq = set * NPQ + a;
            if (pq >= PQ) pq = PQ - 1;           // clamp; skipped at store
            float w = ws[kk * PQ + pq];          // warp-uniform -> broadcast
            acc[a][0] = fmaf(w, t4.x, acc[a][0]);
            acc[a][1] = fmaf(w, t4.y, acc[a][1]);
            acc[a][2] = fmaf(w, t4.z, acc[a][2]);
            acc[a][3] = fmaf(w, t4.w, acc[a][3]);
        }
    }

    const int uv = lane * 4;
    const int u = uv >> 4, v = uv & 15;          // 4 consecutive v, same u
    float* ob = out + (long long)b * 65536 + blk_off(J) * 256 + blk_off(K);
#pragma unroll
    for (int a = 0; a < NPQ; ++a) {
        int pq = set * NPQ + a;
        if (pq < PQ) {
            int p = pq / Q, q = pq - (pq / Q) * Q;
            int row = u * P + p;
            int colb = v * Q + q;
            float* o = ob + row * 256 + colb;
            o[0]     = acc[a][0];
            o[Q]     = acc[a][1];
            o[2 * Q] = acc[a][2];
            o[3 * Q] = acc[a][3];
        }
    }
}

// ============================================================================
extern "C" void kernel_launch(void* const* d_in, const int* in_sizes, int n_in,
                              void* d_out, int out_size)
{
    const float* x = (const float*)d_in[0];
    const float* w = (const float*)d_in[1];
    float* out = (float*)d_out;
    (void)in_sizes; (void)n_in; (void)out_size;

    wigner_init_kernel<<<40, 256>>>();

    phase1_kernel<1><<<dim3(16 * 1, 4 * ninstr_of(0)), 256>>>(
        x, w, group_first(0) * 32768, t_base_of(group_first(0)), xoff_of(0));
    phase1_kernel<3><<<dim3(16 * 3, 4 * ninstr_of(1)), 256>>>(
        x, w, group_first(1) * 32768, t_base_of(group_first(1)), xoff_of(1));
    phase1_kernel<5><<<dim3(16 * 5, 4 * ninstr_of(2)), 256>>>(
        x, w, group_first(2) * 32768, t_base_of(group_first(2)), xoff_of(2));
    phase1_kernel<7><<<dim3(16 * 7, 4 * ninstr_of(3)), 256>>>(
        x, w, group_first(3) * 32768, t_base_of(group_first(3)), xoff_of(3));
    phase1_kernel<9><<<dim3(16 * 9, 4 * ninstr_of(4)), 256>>>(
        x, w, group_first(4) * 32768, t_base_of(group_first(4)), xoff_of(4));

    phase2_kernel<0, 0><<<2048, 256>>>(out);
    phase2_kernel<0, 1><<<2048, 256>>>(out);
    phase2_kernel<0, 2><<<2048, 256>>>(out);
    phase2_kernel<0, 3><<<2048, 256>>>(out);
    phase2_kernel<1, 0><<<2048, 256>>>(out);
    phase2_kernel<1, 1><<<2048, 256>>>(out);
    phase2_kernel<1, 2><<<2048, 256>>>(out);
    phase2_kernel<1, 3><<<2048, 256>>>(out);
    phase2_kernel<2, 0><<<2048, 256>>>(out);
    phase2_kernel<2, 1><<<2048, 256>>>(out);
    phase2_kernel<2, 2><<<2048, 256>>>(out);
    phase2_kernel<2, 3><<<2048, 256>>>(out);
    phase2_kernel<3, 0><<<2048, 256>>>(out);
    phase2_kernel<3, 1><<<2048, 256>>>(out);
    phase2_kernel<3, 2><<<2048, 256>>>(out);
    phase2_kernel<3, 3><<<2048, 256>>>(out);
}

// round 9
// speedup vs baseline: 1.1572x; 1.1572x over previous
#include <cuda_runtime.h>

// ============================================================================
// Expansion (e3nn): MUL_IN=128, IN_LS=0..4 (IN_DIM=3200), MUL_OUT=16,
// OUT_LS=0..3 (OUT_DIM=256), BATCH=2048. 40 instrs (i-major).
//
//   init:   real Wigner-3j tables on device (fp64, exact reference formula)
//   trans:  xT[group i][kk][m=(b*L+r)] = x[b,kk,r]   (coalesced phase1 A reads)
//   phase1: per i-group GEMM  t[(b,r), uv] = x^T W / 128   (f32x2 packed FMA)
//   phase2: per (b,(J,K)) CTA: out = sum w3j * t, smem-staged coalesced stores
// ============================================================================

#define DHC __host__ __device__ constexpr

DHC bool instr_valid(int i, int j, int k) {
    int d = j > k ? j - k : k - j;
    return d <= i && i <= j + k;
}
DHC int instr_id(int i, int j, int k) {
    int c = 0;
    for (int a = 0; a < 5; ++a)
        for (int b = 0; b < 4; ++b)
            for (int g = 0; g < 4; ++g)
                if (instr_valid(a, b, g)) {
                    if (a == i && b == j && g == k) return c;
                    ++c;
                }
    return -1;
}
DHC long long t_base_of(int id) {
    int c = 0; long long s = 0;
    for (int a = 0; a < 5; ++a)
        for (int b = 0; b < 4; ++b)
            for (int g = 0; g < 4; ++g)
                if (instr_valid(a, b, g)) {
                    if (c == id) return s * 524288LL;   // 2048*256
                    s += 2 * a + 1; ++c;
                }
    return 0;
}
DHC int w3j_off_of(int id) {
    int c = 0, s = 0;
    for (int a = 0; a < 5; ++a)
        for (int b = 0; b < 4; ++b)
            for (int g = 0; g < 4; ++g)
                if (instr_valid(a, b, g)) {
                    if (c == id) return s;
                    s += (2 * b + 1) * (2 * g + 1) * (2 * a + 1); ++c;
                }
    return 0;
}
DHC int blk_off(int l) { return l == 0 ? 0 : l == 1 ? 16 : l == 2 ? 64 : 144; }
DHC int sum_L(int J, int K) {
    int s = 0;
    for (int i = 0; i < 5; ++i) if (instr_valid(i, J, K)) s += 2 * i + 1;
    return s;
}
DHC int xoff_of(int i) { int s = 0; for (int l = 0; l < i; ++l) s += 2 * l + 1; return 128 * s; }
DHC int ninstr_of(int i) {
    int c = 0;
    for (int b = 0; b < 4; ++b) for (int g = 0; g < 4; ++g) if (instr_valid(i, b, g)) ++c;
    return c;
}
DHC int group_first(int i) {
    for (int b = 0; b < 4; ++b) for (int g = 0; g < 4; ++g)
        if (instr_valid(i, b, g)) return instr_id(i, b, g);
    return 0;
}
// xT base (floats) for group i: 128*2048*sum_{l<i}(2l+1)
DHC long long xt_base_of(int i) {
    long long s = 0;
    for (int l = 0; l < i; ++l) s += 2 * l + 1;
    return 262144LL * s;
}

// ---------------- device scratch ----------------
__device__ float g_t[110100480];     // 440 MB
__device__ float g_xT[6553600];      // 26 MB
__device__ float g_w3j[5110];

// ---------------- f32x2 helpers ----------------
__device__ __forceinline__ unsigned long long pack2(float lo, float hi) {
    unsigned long long r;
    asm("mov.b64 %0, {%1, %2};" : "=l"(r) : "r"(__float_as_uint(lo)), "r"(__float_as_uint(hi)));
    return r;
}
#define FMA2(acc, a, b) asm("fma.rn.f32x2 %0, %1, %2, %0;" : "+l"(acc) : "l"(a), "l"(b))

// ============================================================================
// Wigner-3j init (fp64)
// ============================================================================
struct cd { double re, im; };
__device__ __forceinline__ cd cmul(cd a, cd b) {
    cd r; r.re = a.re * b.re - a.im * b.im; r.im = a.re * b.im + a.im * b.re; return r;
}
__device__ const double g_fact[13] = {
    1.0, 1.0, 2.0, 6.0, 24.0, 120.0, 720.0, 5040.0, 40320.0, 362880.0,
    3628800.0, 39916800.0, 479001600.0
};
__device__ double su2cg(int j1, int m1, int j2, int m2, int j3, int m3) {
    const double* F = g_fact;
    double C = sqrt((2.0 * j3 + 1.0) * F[j3 + j1 - j2] * F[j3 - j1 + j2] * F[j1 + j2 - j3]
                    * F[j3 + m3] * F[j3 - m3]
                    / (F[j1 + j2 + j3 + 1] * F[j1 - m1] * F[j1 + m1] * F[j2 - m2] * F[j2 + m2]));
    int vmin = -j1 + j2 + m3; if (-j1 + m1 > vmin) vmin = -j1 + m1; if (vmin < 0) vmin = 0;
    int vmax = j2 + j3 + m1;
    if (j3 - j1 + j2 < vmax) vmax = j3 - j1 + j2;
    if (j3 + m3 < vmax) vmax = j3 + m3;
    double S = 0.0;
    for (int v = vmin; v <= vmax; ++v) {
        double sgn = ((v + j2 + m2) & 1) ? -1.0 : 1.0;
        S += sgn * F[j2 + j3 + m1 - v] * F[j1 - m1 + v]
             / (F[v] * F[j3 - j1 + j2 - v] * F[j3 + m3 - v] * F[v + j1 - j2 - m3]);
    }
    return C * S;
}
__device__ cd q_ent(int l, int r, int c) {
    const double s = 0.70710678118654752440;
    int m = r - l;
    cd v; v.re = 0.0; v.im = 0.0;
    if (m < 0) {
        if (c == l - m)      { v.re = s; }
        else if (c == l + m) { v.im = -s; }
    } else if (m == 0) {
        if (c == l) v.re = 1.0;
    } else {
        double sg = (m & 1) ? -1.0 : 1.0;
        if (c == l + m)      { v.re = sg * s; }
        else if (c == l - m) { v.im = sg * s; }
    }
    int ph = l & 3;
    cd o = v;
    if (ph == 1)      { o.re = v.im;  o.im = -v.re; }
    else if (ph == 2) { o.re = -v.re; o.im = -v.im; }
    else if (ph == 3) { o.re = -v.im; o.im = v.re; }
    return o;
}
__global__ void __launch_bounds__(256) wigner_init_kernel() {
    __shared__ double vals[1225];
    __shared__ double red[256];
    const int tid = threadIdx.x;
    const int id = blockIdx.x;
    int l1 = 0, l2 = 0, l3 = 0;
    {
        int c = 0;
        for (int a = 0; a < 5; ++a)
            for (int bb = 0; bb < 4; ++bb)
                for (int g = 0; g < 4; ++g)
                    if (instr_valid(a, bb, g)) {
                        if (c == id) { l3 = a; l1 = bb; l2 = g; }
                        ++c;
                    }
    }
    const int P = 2 * l1 + 1, Q2 = 2 * l2 + 1, R = 2 * l3 + 1;
    const int n = P * Q2 * R;
    double ss = 0.0;
    for (int e = tid; e < n; e += 256) {
        int jj = e / (Q2 * R);
        int rem = e - jj * (Q2 * R);
        int ll = rem / R;
        int mm = rem - ll * R;
        cd s; s.re = 0.0; s.im = 0.0;
        for (int i1 = 0; i1 < P; ++i1) {
            cd q1 = q_ent(l1, i1, jj);
            if (q1.re == 0.0 && q1.im == 0.0) continue;
            int m1 = i1 - l1;
            for (int k1 = 0; k1 < Q2; ++k1) {
                int m2 = k1 - l2;
                int m3 = m1 + m2;
                if (m3 < -l3 || m3 > l3) continue;
                cd q2 = q_ent(l2, k1, ll);
                if (q2.re == 0.0 && q2.im == 0.0) continue;
                cd q3 = q_ent(l3, l3 + m3, mm);
                if (q3.re == 0.0 && q3.im == 0.0) continue;
                double cg = su2cg(l1, m1, l2, m2, l3, m3);
                if (cg == 0.0) continue;
                cd q3c; q3c.re = q3.re; q3c.im = -q3.im;
                cd t = cmul(cmul(q1, q2), q3c);
                s.re += cg * t.re;
                s.im += cg * t.im;
            }
        }
        vals[e] = s.re;
        ss += s.re * s.re;
    }
    red[tid] = ss;
    __syncthreads();
    for (int st = 128; st > 0; st >>= 1) {
        if (tid < st) red[tid] += red[tid + st];
        __syncthreads();
    }
    const double inv = 1.0 / sqrt(red[0]);
    const int wo = w3j_off_of(id);
    for (int e = tid; e < n; e += 256)
        g_w3j[wo + e] = (float)(vals[e] * inv);
}

// ============================================================================
// Transpose: xT[kk][m] = x[b*3200 + xoff + kk*L + r],  m = b*L + r
// ============================================================================
template<int L>
__global__ void __launch_bounds__(256) transpose_kernel(
    const float* __restrict__ x, long long xtb, int xoff)
{
    const int M = 2048 * L;
    int idx = blockIdx.x * 256 + threadIdx.x;           // over 128*M
    int kk = idx / M;
    int m = idx - kk * M;
    int b = m / L, r = m - b * L;
    g_xT[xtb + idx] = x[b * 3200 + xoff + kk * L + r];
}

// ============================================================================
// Phase 1: 128x128 CTA tile, 256 threads, 8x8/thread via f32x2 packed FMA.
// ============================================================================
template<int L>
__global__ void __launch_bounds__(256, 2) phase1_kernel(
    const float* __restrict__ wflat, int woff0, long long tb0, long long xtb)
{
    constexpr int M = 2048 * L;
    __shared__ __align__(16) float As[32][128];
    __shared__ __align__(16) float Bs[32][128];
    const int tid = threadIdx.x;
    const int m0 = blockIdx.x * 128;
    const int il = blockIdx.y >> 1;
    const int uv0 = (blockIdx.y & 1) * 128;
    const float* wB = wflat + woff0 + (size_t)il * 32768 + uv0;
    const float* xA = g_xT + xtb + m0;
    float* tC = g_t + tb0 + (long long)il * (2048LL * L * 256);
    const int ty = tid >> 4, tx = tid & 15;

    unsigned long long acc2[8][4];
#pragma unroll
    for (int u = 0; u < 8; ++u)
#pragma unroll
        for (int v = 0; v < 4; ++v) acc2[u][v] = 0ULL;

    for (int k0 = 0; k0 < 128; k0 += 32) {
#pragma unroll
        for (int it = 0; it < 16; ++it) {
            int e = tid + 256 * it;
            int ml = e & 127, kk = e >> 7;
            As[kk][ml] = xA[(long long)(k0 + kk) * M + ml];
        }
#pragma unroll
        for (int it = 0; it < 16; ++it) {
            int e = tid + 256 * it;
            int nl = e & 127, kk = e >> 7;
            Bs[kk][nl] = wB[(k0 + kk) * 256 + nl];
        }
        __syncthreads();
#pragma unroll
        for (int kk = 0; kk < 32; ++kk) {
            float4 a0 = *(const float4*)(&As[kk][ty * 8]);
            float4 a1 = *(const float4*)(&As[kk][ty * 8 + 4]);
            ulonglong2 b01 = *(const ulonglong2*)(&Bs[kk][tx * 8]);
            ulonglong2 b23 = *(const ulonglong2*)(&Bs[kk][tx * 8 + 4]);
            unsigned long long bp[4] = { b01.x, b01.y, b23.x, b23.y };
            float av[8] = { a0.x, a0.y, a0.z, a0.w, a1.x, a1.y, a1.z, a1.w };
#pragma unroll
            for (int u = 0; u < 8; ++u) {
                unsigned long long ad = pack2(av[u], av[u]);
                FMA2(acc2[u][0], ad, bp[0]);
                FMA2(acc2[u][1], ad, bp[1]);
                FMA2(acc2[u][2], ad, bp[2]);
                FMA2(acc2[u][3], ad, bp[3]);
            }
        }
        __syncthreads();
    }
#pragma unroll
    for (int u = 0; u < 8; ++u) {
        int m = m0 + ty * 8 + u;
        float2 p0 = *(float2*)&acc2[u][0];
        float2 p1 = *(float2*)&acc2[u][1];
        float2 p2 = *(float2*)&acc2[u][2];
        float2 p3 = *(float2*)&acc2[u][3];
        float4 o0, o1;
        o0.x = p0.x * 0.0078125f; o0.y = p0.y * 0.0078125f;
        o0.z = p1.x * 0.0078125f; o0.w = p1.y * 0.0078125f;
        o1.x = p2.x * 0.0078125f; o1.y = p2.y * 0.0078125f;
        o1.z = p3.x * 0.0078125f; o1.w = p3.y * 0.0078125f;
        float* dst = tC + (long long)m * 256 + uv0 + tx * 8;
        *(float4*)dst = o0;
        *(float4*)(dst + 4) = o1;
    }
}

// ============================================================================
// Phase 2: compute in regs (broadcast-w FMA), stage in smem, coalesced flush.
// ============================================================================
template<int J, int K>
__global__ void __launch_bounds__(256) phase2_kernel(float* __restrict__ out)
{
    constexpr int P = 2 * J + 1, Q = 2 * K + 1, PQ = P * Q;
    constexpr int SUML = sum_L(J, K);
    constexpr int NPQ = (PQ + 3) / 4;
    constexpr int PB = (PQ * 1024 > 40000) ? (P + 1) / 2 : P;   // p-rows per flush batch
    constexpr int NBATCH = (P + PB - 1) / PB;
    constexpr int R1 = SUML * 256 + SUML * PQ;
    constexpr int R2 = PB * Q * 256;
    constexpr int REGION = (R1 > R2) ? R1 : R2;
    __shared__ __align__(16) float sm[REGION];
    float* ts = sm;
    float* ws = sm + SUML * 256;
    const int tid = threadIdx.x;
    const int b = blockIdx.x;

    int kb = 0;
#pragma unroll
    for (int i = 0; i < 5; ++i) {
        if (!instr_valid(i, J, K)) continue;
        const int Ri = 2 * i + 1;
        const int id = instr_id(i, J, K);
        const long long tb = t_base_of(id) + (long long)b * (Ri * 256);
        const float4* src = (const float4*)(g_t + tb);
        float4* dst = (float4*)(ts + kb * 256);
        for (int idx = tid; idx < Ri * 64; idx += 256) dst[idx] = src[idx];
        const int wo = w3j_off_of(id);
        for (int idx = tid; idx < PQ * Ri; idx += 256) {
            int pq = idx / Ri, r = idx - pq * Ri;
            ws[(kb + r) * PQ + pq] = g_w3j[wo + idx];
        }
        kb += Ri;
    }
    __syncthreads();

    const int lane = tid & 63;
    const int set = tid >> 6;

    float acc[NPQ][4];
#pragma unroll
    for (int a = 0; a < NPQ; ++a)
#pragma unroll
        for (int c = 0; c < 4; ++c) acc[a][c] = 0.0f;

#pragma unroll
    for (int kk = 0; kk < SUML; ++kk) {
        float4 t4 = ((const float4*)ts)[kk * 64 + lane];
#pragma unroll
        for (int a = 0; a < NPQ; ++a) {
            int pq = set * NPQ + a;
            if (pq >= PQ) pq = PQ - 1;
            float w = ws[kk * PQ + pq];
            acc[a][0] = fmaf(w, t4.x, acc[a][0]);
            acc[a][1] = fmaf(w, t4.y, acc[a][1]);
            acc[a][2] = fmaf(w, t4.z, acc[a][2]);
            acc[a][3] = fmaf(w, t4.w, acc[a][3]);
        }
    }

    float* ob = out + (long long)b * 65536 + blk_off(J) * 256 + blk_off(K);
#pragma unroll
    for (int nb = 0; nb < NBATCH; ++nb) {
        const int p0 = nb * PB;
        const int p1 = (p0 + PB < P) ? p0 + PB : P;
        __syncthreads();               // ts reads / previous flush complete
        // stage this batch's acc rows into smem (aliases ts region)
#pragma unroll
        for (int a = 0; a < NPQ; ++a) {
            int pq = set * NPQ + a;
            if (pq < PQ) {
                int p = pq / Q;
                if (p >= p0 && p < p1) {
                    float4 v4;
                    v4.x = acc[a][0]; v4.y = acc[a][1];
                    v4.z = acc[a][2]; v4.w = acc[a][3];
                    ((float4*)sm)[(pq - p0 * Q) * 64 + lane] = v4;
                }
            }
        }
        __syncthreads();
        // coalesced flush: float4 positions (r_o, c4) of the 16P x 16Q block
        for (int idx = tid; idx < 64 * PQ; idx += 256) {
            int r_o = idx / (4 * Q);
            int c4 = idx - r_o * (4 * Q);
            int u = r_o / P;
            int p = r_o - u * P;
            if (p >= p0 && p < p1) {
                const float* bb = sm + (p - p0) * Q * 256 + u * 16;
                float4 o;
                {
                    int c = 4 * c4 + 0; int v = c / Q; int q = c - v * Q;
                    o.x = bb[q * 256 + v];
                }
                {
                    int c = 4 * c4 + 1; int v = c / Q; int q = c - v * Q;
                    o.y = bb[q * 256 + v];
                }
                {
                    int c = 4 * c4 + 2; int v = c / Q; int q = c - v * Q;
                    o.z = bb[q * 256 + v];
                }
                {
                    int c = 4 * c4 + 3; int v = c / Q; int q = c - v * Q;
                    o.w = bb[q * 256 + v];
                }
                *(float4*)(ob + r_o * 256 + 4 * c4) = o;
            }
        }
    }
}

// ============================================================================
extern "C" void kernel_launch(void* const* d_in, const int* in_sizes, int n_in,
                              void* d_out, int out_size)
{
    const float* x = (const float*)d_in[0];
    const float* w = (const float*)d_in[1];
    float* out = (float*)d_out;
    (void)in_sizes; (void)n_in; (void)out_size;

    wigner_init_kernel<<<40, 256>>>();

    transpose_kernel<1><<<1024 * 1, 256>>>(x, xt_base_of(0), xoff_of(0));
    transpose_kernel<3><<<1024 * 3, 256>>>(x, xt_base_of(1), xoff_of(1));
    transpose_kernel<5><<<1024 * 5, 256>>>(x, xt_base_of(2), xoff_of(2));
    transpose_kernel<7><<<1024 * 7, 256>>>(x, xt_base_of(3), xoff_of(3));
    transpose_kernel<9><<<1024 * 9, 256>>>(x, xt_base_of(4), xoff_of(4));

    phase1_kernel<1><<<dim3(16 * 1, 2 * ninstr_of(0)), 256>>>(
        w, group_first(0) * 32768, t_base_of(group_first(0)), xt_base_of(0));
    phase1_kernel<3><<<dim3(16 * 3, 2 * ninstr_of(1)), 256>>>(
        w, group_first(1) * 32768, t_base_of(group_first(1)), xt_base_of(1));
    phase1_kernel<5><<<dim3(16 * 5, 2 * ninstr_of(2)), 256>>>(
        w, group_first(2) * 32768, t_base_of(group_first(2)), xt_base_of(2));
    phase1_kernel<7><<<dim3(16 * 7, 2 * ninstr_of(3)), 256>>>(
        w, group_first(3) * 32768, t_base_of(group_first(3)), xt_base_of(3));
    phase1_kernel<9><<<dim3(16 * 9, 2 * ninstr_of(4)), 256>>>(
        w, group_first(4) * 32768, t_base_of(group_first(4)), xt_base_of(4));

    phase2_kernel<0, 0><<<2048, 256>>>(out);
    phase2_kernel<0, 1><<<2048, 256>>>(out);
    phase2_kernel<0, 2><<<2048, 256>>>(out);
    phase2_kernel<0, 3><<<2048, 256>>>(out);
    phase2_kernel<1, 0><<<2048, 256>>>(out);
    phase2_kernel<1, 1><<<2048, 256>>>(out);
    phase2_kernel<1, 2><<<2048, 256>>>(out);
    phase2_kernel<1, 3><<<2048, 256>>>(out);
    phase2_kernel<2, 0><<<2048, 256>>>(out);
    phase2_kernel<2, 1><<<2048, 256>>>(out);
    phase2_kernel<2, 2><<<2048, 256>>>(out);
    phase2_kernel<2, 3><<<2048, 256>>>(out);
    phase2_kernel<3, 0><<<2048, 256>>>(out);
    phase2_kernel<3, 1><<<2048, 256>>>(out);
    phase2_kernel<3, 2><<<2048, 256>>>(out);
    phase2_kernel<3, 3><<<2048, 256>>>(out);
}

// round 11
// speedup vs baseline: 1.4304x; 1.2361x over previous
#include <cuda_runtime.h>
#include <cuda_bf16.h>
#include <cstdint>

// ============================================================================
// Expansion (e3nn): MUL_IN=128, IN_LS=0..4, MUL_OUT=16, OUT_LS=0..3, B=2048.
//   init:   real Wigner-3j tables on device (fp64, exact reference formula)
//   prep:   bf16 hi/lo of x (m-major) + W^T (n-major)   [tensor-core path]
//   trans:  fp32 xT (k-major)                            [FFMA fallback path]
//   phase1: t[(b,r), uv] = x W / 128
//           - sm_103a build: tcgen05 bf16-split (Ah*Bh + Al*Bh + Ah*Bl)
//           - plain sm_103 build: f32x2 packed-FMA GEMM (proven R9 path)
//   phase2: merged kernel: out = sum w3j * t, smem-staged coalesced stores
// ============================================================================

#if defined(__CUDA_ARCH_FEAT_SM103_ALL)
#define HAS_TC 1
#else
#define HAS_TC 0
#endif

#define DHC __host__ __device__ constexpr

DHC bool instr_valid(int i, int j, int k) {
    int d = j > k ? j - k : k - j;
    return d <= i && i <= j + k;
}
DHC int instr_id(int i, int j, int k) {
    int c = 0;
    for (int a = 0; a < 5; ++a)
        for (int b = 0; b < 4; ++b)
            for (int g = 0; g < 4; ++g)
                if (instr_valid(a, b, g)) {
                    if (a == i && b == j && g == k) return c;
                    ++c;
                }
    return -1;
}
DHC long long t_base_of(int id) {
    int c = 0; long long s = 0;
    for (int a = 0; a < 5; ++a)
        for (int b = 0; b < 4; ++b)
            for (int g = 0; g < 4; ++g)
                if (instr_valid(a, b, g)) {
                    if (c == id) return s * 524288LL;   // 2048*256
                    s += 2 * a + 1; ++c;
                }
    return 0;
}
DHC int w3j_off_of(int id) {
    int c = 0, s = 0;
    for (int a = 0; a < 5; ++a)
        for (int b = 0; b < 4; ++b)
            for (int g = 0; g < 4; ++g)
                if (instr_valid(a, b, g)) {
                    if (c == id) return s;
                    s += (2 * b + 1) * (2 * g + 1) * (2 * a + 1); ++c;
                }
    return 0;
}
DHC int blk_off(int l) { return l == 0 ? 0 : l == 1 ? 16 : l == 2 ? 64 : 144; }
DHC int sum_L(int J, int K) {
    int s = 0;
    for (int i = 0; i < 5; ++i) if (instr_valid(i, J, K)) s += 2 * i + 1;
    return s;
}
DHC int xoff_of(int i) { int s = 0; for (int l = 0; l < i; ++l) s += 2 * l + 1; return 128 * s; }
DHC int ninstr_of(int i) {
    int c = 0;
    for (int b = 0; b < 4; ++b) for (int g = 0; g < 4; ++g) if (instr_valid(i, b, g)) ++c;
    return c;
}
DHC int group_first(int i) {
    for (int b = 0; b < 4; ++b) for (int g = 0; g < 4; ++g)
        if (instr_valid(i, b, g)) return instr_id(i, b, g);
    return 0;
}
DHC long long xm_base_of(int i) {   // element base for group i (all x scratch arrays)
    long long s = 0;
    for (int l = 0; l < i; ++l) s += 2 * l + 1;
    return 262144LL * s;            // 2048*128 * sum(2l+1)
}

// ---------------- device scratch ----------------
__device__ float g_t[110100480];                         // 440 MB
__device__ float g_xT[6553600];                          // fp32 x, k-major (fallback)
__device__ __align__(16) __nv_bfloat16 g_xh[6553600];    // x hi, [group][m][k]
__device__ __align__(16) __nv_bfloat16 g_xl[6553600];    // x lo
__device__ __align__(16) __nv_bfloat16 g_wh[1310720];    // W^T hi, [instr][n][k]
__device__ __align__(16) __nv_bfloat16 g_wl[1310720];    // W^T lo
__device__ float g_w3j[5110];

// ---------------- f32x2 helpers (base sm_100+, safe on both targets) --------
__device__ __forceinline__ unsigned long long pack2(float lo, float hi) {
    unsigned long long r;
    asm("mov.b64 %0, {%1, %2};" : "=l"(r) : "r"(__float_as_uint(lo)), "r"(__float_as_uint(hi)));
    return r;
}
#define FMA2(acc, a, b) asm("fma.rn.f32x2 %0, %1, %2, %0;" : "+l"(acc) : "l"(a), "l"(b))

// ============================================================================
// sm_103a-only helpers (never instantiated on plain sm_103 compile)
// ============================================================================
__device__ __forceinline__ uint32_t smem_u32(const void* p) {
    uint32_t a;
    asm("{ .reg .u64 t; cvta.to.shared.u64 t, %1; cvt.u32.u64 %0, t; }" : "=r"(a) : "l"(p));
    return a;
}
__device__ __forceinline__ uint32_t elect_one_pred() {
#if HAS_TC
    uint32_t pred;
    asm volatile(
        "{\n\t.reg .pred p;\n\telect.sync _|p, 0xFFFFFFFF;\n\tselp.b32 %0, 1, 0, p;\n\t}"
        : "=r"(pred));
    return pred;
#else
    return (threadIdx.x & 31) == 0;
#endif
}
#if HAS_TC
#define TCGEN05_ALLOC(smem_addr, nCols) \
    asm volatile("tcgen05.alloc.cta_group::1.sync.aligned.shared::cta.b32 [%0], %1;" \
                 :: "r"((uint32_t)(smem_addr)), "r"((uint32_t)(nCols)) : "memory")
#define TCGEN05_DEALLOC(tmem_addr, nCols) \
    asm volatile("tcgen05.dealloc.cta_group::1.sync.aligned.b32 %0, %1;" \
                 :: "r"(tmem_addr), "r"((uint32_t)(nCols)))
#define TCGEN05_WAIT_ST() asm volatile("tcgen05.wait::st.sync.aligned;" ::: "memory")
#define TCGEN05_WAIT_LD() asm volatile("tcgen05.wait::ld.sync.aligned;" ::: "memory")
#define TCGEN05_FENCE_BEFORE() asm volatile("tcgen05.fence::before_thread_sync;" ::: "memory")
#define TCGEN05_FENCE_AFTER()  asm volatile("tcgen05.fence::after_thread_sync;" ::: "memory")
#define TCGEN05_COMMIT(mbar) \
    asm volatile("tcgen05.commit.cta_group::1.mbarrier::arrive::one.shared::cluster.b64 [%0];" \
                 :: "r"((uint32_t)(mbar)) : "memory")
#define MBARRIER_INIT(mbar, count) \
    asm volatile("mbarrier.init.shared.b64 [%0], %1;" \
                 :: "r"((uint32_t)(mbar)), "r"((uint32_t)(count)) : "memory")
#define MBARRIER_INVAL(mbar) \
    asm volatile("mbarrier.inval.shared.b64 [%0];" :: "r"((uint32_t)(mbar)) : "memory")
#define MBARRIER_WAIT_PARITY(mbar_smem_addr, phase_parity) do { \
    uint32_t _mbar = (uint32_t)(mbar_smem_addr); \
    uint32_t _parity = (uint32_t)(phase_parity); \
    uint32_t _done; \
    asm volatile( \
        "{\n\t.reg .pred p;\n\t" \
        "mbarrier.try_wait.parity.acquire.cta.shared::cta.b64 p, [%1], %2;\n\t" \
        "selp.b32 %0, 1, 0, p;\n\t}" \
        : "=r"(_done) : "r"(_mbar), "r"(_parity) : "memory"); \
    if (!_done) { \
        asm volatile( \
            "{\n\t.reg .pred P1;\n\t" \
            "WAIT_LOOP_%=:\n\t" \
            "mbarrier.try_wait.parity.acquire.cta.shared::cta.b64 P1, [%0], %1, 0x989680;\n\t" \
            "@P1 bra.uni WAIT_DONE_%=;\n\t" \
            "bra.uni WAIT_LOOP_%=;\n\t" \
            "WAIT_DONE_%=:\n\t}" \
            :: "r"(_mbar), "r"(_parity) : "memory"); \
    } \
} while (0)
#define TCGEN05_MMA_F16(d_tmem, a_tmem, b_smem_desc, idesc, enable_d) do { \
    uint32_t _enable = (enable_d) ? 1 : 0; \
    uint32_t _zero = 0; \
    asm volatile( \
        "{\n\t.reg .pred p;\n\tsetp.ne.u32 p, %6, 0;\n\t" \
        "tcgen05.mma.cta_group::1.kind::f16 [%0], [%1], %2, %3, " \
        "{%4, %4, %4, %4}, p;\n\t}" \
        :: "r"(d_tmem), "r"(a_tmem), "l"(b_smem_desc), "r"(idesc), \
           "r"(_zero), "r"(_zero), "r"(_enable) \
        : "memory"); \
} while (0)
#define TCGEN05_LD_32X32B_X32(r, tmem_addr) \
    asm volatile( \
        "tcgen05.ld.sync.aligned.32x32b.x32.b32 " \
        "{%0, %1, %2, %3, %4, %5, %6, %7, " \
        " %8, %9, %10, %11, %12, %13, %14, %15, " \
        " %16, %17, %18, %19, %20, %21, %22, %23, " \
        " %24, %25, %26, %27, %28, %29, %30, %31}, [%32];" \
        : "=r"((r)[0]),  "=r"((r)[1]),  "=r"((r)[2]),  "=r"((r)[3]), \
          "=r"((r)[4]),  "=r"((r)[5]),  "=r"((r)[6]),  "=r"((r)[7]), \
          "=r"((r)[8]),  "=r"((r)[9]),  "=r"((r)[10]), "=r"((r)[11]), \
          "=r"((r)[12]), "=r"((r)[13]), "=r"((r)[14]), "=r"((r)[15]), \
          "=r"((r)[16]), "=r"((r)[17]), "=r"((r)[18]), "=r"((r)[19]), \
          "=r"((r)[20]), "=r"((r)[21]), "=r"((r)[22]), "=r"((r)[23]), \
          "=r"((r)[24]), "=r"((r)[25]), "=r"((r)[26]), "=r"((r)[27]), \
          "=r"((r)[28]), "=r"((r)[29]), "=r"((r)[30]), "=r"((r)[31]) \
        : "r"(tmem_addr))
#define TCGEN05_ST_32X32B_X64(tmem_addr, r) \
    asm volatile( \
        "tcgen05.st.sync.aligned.32x32b.x64.b32 [%0], " \
        "{%1, %2, %3, %4, %5, %6, %7, %8, " \
        " %9, %10, %11, %12, %13, %14, %15, %16, " \
        " %17, %18, %19, %20, %21, %22, %23, %24, " \
        " %25, %26, %27, %28, %29, %30, %31, %32, " \
        " %33, %34, %35, %36, %37, %38, %39, %40, " \
        " %41, %42, %43, %44, %45, %46, %47, %48, " \
        " %49, %50, %51, %52, %53, %54, %55, %56, " \
        " %57, %58, %59, %60, %61, %62, %63, %64};" \
        :: "r"(tmem_addr), \
           "r"((r)[0]),  "r"((r)[1]),  "r"((r)[2]),  "r"((r)[3]), \
           "r"((r)[4]),  "r"((r)[5]),  "r"((r)[6]),  "r"((r)[7]), \
           "r"((r)[8]),  "r"((r)[9]),  "r"((r)[10]), "r"((r)[11]), \
           "r"((r)[12]), "r"((r)[13]), "r"((r)[14]), "r"((r)[15]), \
           "r"((r)[16]), "r"((r)[17]), "r"((r)[18]), "r"((r)[19]), \
           "r"((r)[20]), "r"((r)[21]), "r"((r)[22]), "r"((r)[23]), \
           "r"((r)[24]), "r"((r)[25]), "r"((r)[26]), "r"((r)[27]), \
           "r"((r)[28]), "r"((r)[29]), "r"((r)[30]), "r"((r)[31]), \
           "r"((r)[32]), "r"((r)[33]), "r"((r)[34]), "r"((r)[35]), \
           "r"((r)[36]), "r"((r)[37]), "r"((r)[38]), "r"((r)[39]), \
           "r"((r)[40]), "r"((r)[41]), "r"((r)[42]), "r"((r)[43]), \
           "r"((r)[44]), "r"((r)[45]), "r"((r)[46]), "r"((r)[47]), \
           "r"((r)[48]), "r"((r)[49]), "r"((r)[50]), "r"((r)[51]), \
           "r"((r)[52]), "r"((r)[53]), "r"((r)[54]), "r"((r)[55]), \
           "r"((r)[56]), "r"((r)[57]), "r"((r)[58]), "r"((r)[59]), \
           "r"((r)[60]), "r"((r)[61]), "r"((r)[62]), "r"((r)[63]) \
        : "memory")
#endif  // HAS_TC
static constexpr unsigned long long SMEM_DESC_BASE_SW128 =
    (2ULL << 61) | (1ULL << 46) | (64ULL << 32) | (1ULL << 16);
#define MAKE_SMEM_DESC(base_addr) \
    (SMEM_DESC_BASE_SW128 | ((unsigned long long)((base_addr) >> 4) & 0x3FFF))
#define SMEM_SWIZZLE_128B(o) ((o) ^ (((o) >> 3) & 0x70))

// idesc kind::f16: F32 accum, BF16 a/b, N=128, M=128
static constexpr uint32_t IDESC_BF16_M128_N128 =
    (1u << 4) | (1u << 7) | (1u << 10) | (16u << 17) | (8u << 24);

// ============================================================================
// Wigner-3j init (fp64)
// ============================================================================
struct cd { double re, im; };
__device__ __forceinline__ cd cmul(cd a, cd b) {
    cd r; r.re = a.re * b.re - a.im * b.im; r.im = a.re * b.im + a.im * b.re; return r;
}
__device__ const double g_fact[13] = {
    1.0, 1.0, 2.0, 6.0, 24.0, 120.0, 720.0, 5040.0, 40320.0, 362880.0,
    3628800.0, 39916800.0, 479001600.0
};
__device__ double su2cg(int j1, int m1, int j2, int m2, int j3, int m3) {
    const double* F = g_fact;
    double C = sqrt((2.0 * j3 + 1.0) * F[j3 + j1 - j2] * F[j3 - j1 + j2] * F[j1 + j2 - j3]
                    * F[j3 + m3] * F[j3 - m3]
                    / (F[j1 + j2 + j3 + 1] * F[j1 - m1] * F[j1 + m1] * F[j2 - m2] * F[j2 + m2]));
    int vmin = -j1 + j2 + m3; if (-j1 + m1 > vmin) vmin = -j1 + m1; if (vmin < 0) vmin = 0;
    int vmax = j2 + j3 + m1;
    if (j3 - j1 + j2 < vmax) vmax = j3 - j1 + j2;
    if (j3 + m3 < vmax) vmax = j3 + m3;
    double S = 0.0;
    for (int v = vmin; v <= vmax; ++v) {
        double sgn = ((v + j2 + m2) & 1) ? -1.0 : 1.0;
        S += sgn * F[j2 + j3 + m1 - v] * F[j1 - m1 + v]
             / (F[v] * F[j3 - j1 + j2 - v] * F[j3 + m3 - v] * F[v + j1 - j2 - m3]);
    }
    return C * S;
}
__device__ cd q_ent(int l, int r, int c) {
    const double s = 0.70710678118654752440;
    int m = r - l;
    cd v; v.re = 0.0; v.im = 0.0;
    if (m < 0) {
        if (c == l - m)      { v.re = s; }
        else if (c == l + m) { v.im = -s; }
    } else if (m == 0) {
        if (c == l) v.re = 1.0;
    } else {
        double sg = (m & 1) ? -1.0 : 1.0;
        if (c == l + m)      { v.re = sg * s; }
        else if (c == l - m) { v.im = sg * s; }
    }
    int ph = l & 3;
    cd o = v;
    if (ph == 1)      { o.re = v.im;  o.im = -v.re; }
    else if (ph == 2) { o.re = -v.re; o.im = -v.im; }
    else if (ph == 3) { o.re = -v.im; o.im = v.re; }
    return o;
}
__global__ void __launch_bounds__(256) wigner_init_kernel() {
    __shared__ double vals[1225];
    __shared__ double red[256];
    const int tid = threadIdx.x;
    const int id = blockIdx.x;
    int l1 = 0, l2 = 0, l3 = 0;
    {
        int c = 0;
        for (int a = 0; a < 5; ++a)
            for (int bb = 0; bb < 4; ++bb)
                for (int g = 0; g < 4; ++g)
                    if (instr_valid(a, bb, g)) {
                        if (c == id) { l3 = a; l1 = bb; l2 = g; }
                        ++c;
                    }
    }
    const int P = 2 * l1 + 1, Q2 = 2 * l2 + 1, R = 2 * l3 + 1;
    const int n = P * Q2 * R;
    double ss = 0.0;
    for (int e = tid; e < n; e += 256) {
        int jj = e / (Q2 * R);
        int rem = e - jj * (Q2 * R);
        int ll = rem / R;
        int mm = rem - ll * R;
        cd s; s.re = 0.0; s.im = 0.0;
        for (int i1 = 0; i1 < P; ++i1) {
            cd q1 = q_ent(l1, i1, jj);
            if (q1.re == 0.0 && q1.im == 0.0) continue;
            int m1 = i1 - l1;
            for (int k1 = 0; k1 < Q2; ++k1) {
                int m2 = k1 - l2;
                int m3 = m1 + m2;
                if (m3 < -l3 || m3 > l3) continue;
                cd q2 = q_ent(l2, k1, ll);
                if (q2.re == 0.0 && q2.im == 0.0) continue;
                cd q3 = q_ent(l3, l3 + m3, mm);
                if (q3.re == 0.0 && q3.im == 0.0) continue;
                double cg = su2cg(l1, m1, l2, m2, l3, m3);
                if (cg == 0.0) continue;
                cd q3c; q3c.re = q3.re; q3c.im = -q3.im;
                cd t = cmul(cmul(q1, q2), q3c);
                s.re += cg * t.re;
                s.im += cg * t.im;
            }
        }
        vals[e] = s.re;
        ss += s.re * s.re;
    }
    red[tid] = ss;
    __syncthreads();
    for (int st = 128; st > 0; st >>= 1) {
        if (tid < st) red[tid] += red[tid + st];
        __syncthreads();
    }
    const double inv = 1.0 / sqrt(red[0]);
    const int wo = w3j_off_of(id);
    for (int e = tid; e < n; e += 256)
        g_w3j[wo + e] = (float)(vals[e] * inv);
}

// ============================================================================
// Prep kernels
// ============================================================================
template<int L>
__global__ void __launch_bounds__(256) prep_x_kernel(
    const float* __restrict__ x, long long base, int xoff)
{
    long long idx = (long long)blockIdx.x * 256 + threadIdx.x;  // 2048L*128 exact
    int m = (int)(idx >> 7);
    int kk = (int)(idx & 127);
    int b = m / L, r = m - b * L;
    float v = x[b * 3200 + xoff + kk * L + r];
    __nv_bfloat16 hi = __float2bfloat16_rn(v);
    __nv_bfloat16 lo = __float2bfloat16_rn(v - __bfloat162float(hi));
    g_xh[base + idx] = hi;
    g_xl[base + idx] = lo;
}
__global__ void __launch_bounds__(256) prep_w_kernel(const float* __restrict__ w)
{
    int idx = blockIdx.x * 256 + threadIdx.x;   // 40*32768 exact
    int instr = idx >> 15;
    int rem = idx & 32767;
    int n = rem >> 7, k = rem & 127;
    float v = w[instr * 32768 + k * 256 + n];
    __nv_bfloat16 hi = __float2bfloat16_rn(v);
    __nv_bfloat16 lo = __float2bfloat16_rn(v - __bfloat162float(hi));
    g_wh[idx] = hi;
    g_wl[idx] = lo;
}
// fp32 k-major transpose for FFMA fallback: xT[kk][m] = x[b][kk][r]
template<int L>
__global__ void __launch_bounds__(256) transpose_kernel(
    const float* __restrict__ x, long long xtb, int xoff)
{
    const int M = 2048 * L;
    int idx = blockIdx.x * 256 + threadIdx.x;   // 128*M exact
    int kk = idx / M;
    int m = idx - kk * M;
    int b = m / L, r = m - b * L;
    g_xT[xtb + idx] = x[b * 3200 + xoff + kk * L + r];
}

// ============================================================================
// Phase 1 (dual path). grid(16L, 2*n_i), block 256, dyn smem 66560.
// ============================================================================
template<int L>
__global__ void __launch_bounds__(256, 2)
#if HAS_TC
__cluster_dims__(1, 1, 1)
#endif
phase1_kernel(const float* __restrict__ wflat, int instr0, int woff0,
              long long tb0, long long xbase, long long xtb)
{
    extern __shared__ __align__(16) char dyn[];
    const int tid = threadIdx.x;
    const int m0 = blockIdx.x * 128;
    const int il = blockIdx.y >> 1;
    const int nt = blockIdx.y & 1;
    float* tC_base = g_t + tb0 + (long long)il * (2048LL * L * 256);

#if HAS_TC
    // ------------------------------------------------------------- tensor path
    __shared__ uint32_t s_tmem;
    __shared__ __align__(8) unsigned long long s_mbar;
    const int wid = tid >> 5, lid = tid & 31;
    const int instr = instr0 + il;

    const uint32_t dynb = smem_u32(dyn);
    const uint32_t bh = (dynb + 1023u) & ~1023u;
    const uint32_t bl = bh + 32768u;
    char* p_bh = dyn + (bh - dynb);
    char* p_bl = dyn + (bl - dynb);

    if (wid == 0) TCGEN05_ALLOC(smem_u32(&s_tmem), 256);
    if (tid == 0) MBARRIER_INIT(smem_u32(&s_mbar), 1);
    __syncthreads();
    const uint32_t tmem = s_tmem;     // D: cols 0..127, A_hi: 128..191, A_lo: 192..255
    const uint32_t mbar = smem_u32(&s_mbar);

    // A hi/lo -> TMEM (warpgroup 0 only; thread = m-row)
    if (tid < 128) {
        const uint32_t warp_off = ((uint32_t)wid) << 21;
        uint32_t a[64];
        const uint4* src = (const uint4*)(g_xh + xbase + (long long)(m0 + tid) * 128);
#pragma unroll
        for (int i = 0; i < 16; ++i) {
            uint4 v = src[i];
            a[i * 4 + 0] = v.x; a[i * 4 + 1] = v.y; a[i * 4 + 2] = v.z; a[i * 4 + 3] = v.w;
        }
        TCGEN05_ST_32X32B_X64(tmem + 128 + warp_off, a);
        TCGEN05_WAIT_ST();            // regs reused below: stores must complete
        const uint4* src2 = (const uint4*)(g_xl + xbase + (long long)(m0 + tid) * 128);
#pragma unroll
        for (int i = 0; i < 16; ++i) {
            uint4 v = src2[i];
            a[i * 4 + 0] = v.x; a[i * 4 + 1] = v.y; a[i * 4 + 2] = v.z; a[i * 4 + 3] = v.w;
        }
        TCGEN05_ST_32X32B_X64(tmem + 192 + warp_off, a);
        TCGEN05_WAIT_ST();
    }

    // B hi/lo -> SMEM (blocked-atom SW128: atom 8n x 128B; atoms (n>>3) + (c>>3)*16)
    {
        const uint4* srch = (const uint4*)(g_wh + (long long)instr * 32768 + nt * 16384);
        const uint4* srcl = (const uint4*)(g_wl + (long long)instr * 32768 + nt * 16384);
#pragma unroll
        for (int it = 0; it < 8; ++it) {
            int idx = tid + it * 256;            // n*16 + c, 2048 total
            int n = idx >> 4, c = idx & 15;
            uint32_t byte_off = (uint32_t)(((n >> 3) + (c >> 3) * 16) * 1024
                                           + (n & 7) * 128 + (c & 7) * 16);
            uint32_t sw = SMEM_SWIZZLE_128B(byte_off);
            *(uint4*)(p_bh + sw) = srch[idx];
            *(uint4*)(p_bl + sw) = srcl[idx];
        }
    }
    TCGEN05_FENCE_BEFORE();
    __syncthreads();

    // D = Ah*Bh + Al*Bh + Ah*Bl (8 K-steps each)
    if (wid == 0) {
        TCGEN05_FENCE_AFTER();
        const unsigned long long bdh = MAKE_SMEM_DESC(bh);
        const unsigned long long bdl = MAKE_SMEM_DESC(bl);
        const uint32_t offs[8] = {0, 2, 4, 6, 1024, 1026, 1028, 1030};
        if (elect_one_pred()) {
#pragma unroll
            for (int k = 0; k < 8; ++k)
                TCGEN05_MMA_F16(tmem, tmem + 128 + k * 8, bdh + offs[k],
                                IDESC_BF16_M128_N128, k > 0);
#pragma unroll
            for (int k = 0; k < 8; ++k)
                TCGEN05_MMA_F16(tmem, tmem + 192 + k * 8, bdh + offs[k],
                                IDESC_BF16_M128_N128, true);
#pragma unroll
            for (int k = 0; k < 8; ++k)
                TCGEN05_MMA_F16(tmem, tmem + 128 + k * 8, bdl + offs[k],
                                IDESC_BF16_M128_N128, true);
            TCGEN05_COMMIT(mbar);
        }
    }
    __syncthreads();
    MBARRIER_WAIT_PARITY(mbar, 0);
    TCGEN05_FENCE_AFTER();

    // epilogue (warpgroup 0): scale 1/128, store t
    if (tid < 128) {
        float* tC = tC_base + (long long)(m0 + wid * 32 + lid) * 256 + nt * 128;
#pragma unroll
        for (int c4 = 0; c4 < 4; ++c4) {
            uint32_t r[32];
            TCGEN05_LD_32X32B_X32(r, tmem + c4 * 32);
            TCGEN05_WAIT_LD();
#pragma unroll
            for (int j = 0; j < 8; ++j) {
                float4 o;
                o.x = __uint_as_float(r[j * 4 + 0]) * 0.0078125f;
                o.y = __uint_as_float(r[j * 4 + 1]) * 0.0078125f;
                o.z = __uint_as_float(r[j * 4 + 2]) * 0.0078125f;
                o.w = __uint_as_float(r[j * 4 + 3]) * 0.0078125f;
                *(float4*)(tC + c4 * 32 + j * 4) = o;
            }
        }
        TCGEN05_FENCE_BEFORE();
    }
    __syncthreads();
    if (tid == 0) MBARRIER_INVAL(mbar);
    if (wid == 0) TCGEN05_DEALLOC(tmem, 256);

#else
    // ------------------------------------------------------------ FFMA fallback
    constexpr int M = 2048 * L;
    float* As = (float*)dyn;                     // [32][128]
    float* Bs = (float*)(dyn + 16384);           // [32][128]
    const int uv0 = nt * 128;
    const float* wB = wflat + woff0 + (size_t)il * 32768 + uv0;
    const float* xA = g_xT + xtb + m0;
    const int ty = tid >> 4, tx = tid & 15;

    unsigned long long acc2[8][4];
#pragma unroll
    for (int u = 0; u < 8; ++u)
#pragma unroll
        for (int v = 0; v < 4; ++v) acc2[u][v] = 0ULL;

    for (int k0 = 0; k0 < 128; k0 += 32) {
#pragma unroll
        for (int it = 0; it < 16; ++it) {
            int e = tid + 256 * it;
            int ml = e & 127, kk = e >> 7;
            As[kk * 128 + ml] = xA[(long long)(k0 + kk) * M + ml];
        }
#pragma unroll
        for (int it = 0; it < 16; ++it) {
            int e = tid + 256 * it;
            int nl = e & 127, kk = e >> 7;
            Bs[kk * 128 + nl] = wB[(k0 + kk) * 256 + nl];
        }
        __syncthreads();
#pragma unroll
        for (int kk = 0; kk < 32; ++kk) {
            float4 a0 = *(const float4*)(&As[kk * 128 + ty * 8]);
            float4 a1 = *(const float4*)(&As[kk * 128 + ty * 8 + 4]);
            ulonglong2 b01 = *(const ulonglong2*)(&Bs[kk * 128 + tx * 8]);
            ulonglong2 b23 = *(const ulonglong2*)(&Bs[kk * 128 + tx * 8 + 4]);
            unsigned long long bp[4] = { b01.x, b01.y, b23.x, b23.y };
            float av[8] = { a0.x, a0.y, a0.z, a0.w, a1.x, a1.y, a1.z, a1.w };
#pragma unroll
            for (int u = 0; u < 8; ++u) {
                unsigned long long ad = pack2(av[u], av[u]);
                FMA2(acc2[u][0], ad, bp[0]);
                FMA2(acc2[u][1], ad, bp[1]);
                FMA2(acc2[u][2], ad, bp[2]);
                FMA2(acc2[u][3], ad, bp[3]);
            }
        }
        __syncthreads();
    }
#pragma unroll
    for (int u = 0; u < 8; ++u) {
        int m = m0 + ty * 8 + u;
        float2 p0 = *(float2*)&acc2[u][0];
        float2 p1 = *(float2*)&acc2[u][1];
        float2 p2 = *(float2*)&acc2[u][2];
        float2 p3 = *(float2*)&acc2[u][3];
        float4 o0, o1;
        o0.x = p0.x * 0.0078125f; o0.y = p0.y * 0.0078125f;
        o0.z = p1.x * 0.0078125f; o0.w = p1.y * 0.0078125f;
        o1.x = p2.x * 0.0078125f; o1.y = p2.y * 0.0078125f;
        o1.z = p3.x * 0.0078125f; o1.w = p3.y * 0.0078125f;
        float* dst = tC_base + (long long)m * 256 + uv0 + tx * 8;
        *(float4*)dst = o0;
        *(float4*)(dst + 4) = o1;
    }
#endif
}

// ============================================================================
// Phase 2 (merged)
// ============================================================================
template<int J, int K>
__device__ __forceinline__ void phase2_impl(float* __restrict__ out, float* sm)
{
    constexpr int P = 2 * J + 1, Q = 2 * K + 1, PQ = P * Q;
    constexpr int SUML = sum_L(J, K);
    constexpr int NPQ = (PQ + 3) / 4;
    constexpr int PB = (PQ * 1024 > 40000) ? (P + 1) / 2 : P;
    constexpr int NBATCH = (P + PB - 1) / PB;
    float* ts = sm;
    float* ws = sm + SUML * 256;
    const int tid = threadIdx.x;
    const int b = blockIdx.x;

    int kb = 0;
#pragma unroll
    for (int i = 0; i < 5; ++i) {
        if (!instr_valid(i, J, K)) continue;
        const int Ri = 2 * i + 1;
        const int id = instr_id(i, J, K);
        const long long tb = t_base_of(id) + (long long)b * (Ri * 256);
        const float4* src = (const float4*)(g_t + tb);
        float4* dst = (float4*)(ts + kb * 256);
        for (int idx = tid; idx < Ri * 64; idx += 256) dst[idx] = src[idx];
        const int wo = w3j_off_of(id);
        for (int idx = tid; idx < PQ * Ri; idx += 256) {
            int pq = idx / Ri, r = idx - pq * Ri;
            ws[(kb + r) * PQ + pq] = g_w3j[wo + idx];
        }
        kb += Ri;
    }
    __syncthreads();

    const int lane = tid & 63;
    const int set = tid >> 6;

    float acc[NPQ][4];
#pragma unroll
    for (int a = 0; a < NPQ; ++a)
#pragma unroll
        for (int c = 0; c < 4; ++c) acc[a][c] = 0.0f;

#pragma unroll
    for (int kk = 0; kk < SUML; ++kk) {
        float4 t4 = ((const float4*)ts)[kk * 64 + lane];
#pragma unroll
        for (int a = 0; a < NPQ; ++a) {
            int pq = set * NPQ + a;
            if (pq >= PQ) pq = PQ - 1;
            float w = ws[kk * PQ + pq];
            acc[a][0] = fmaf(w, t4.x, acc[a][0]);
            acc[a][1] = fmaf(w, t4.y, acc[a][1]);
            acc[a][2] = fmaf(w, t4.z, acc[a][2]);
            acc[a][3] = fmaf(w, t4.w, acc[a][3]);
        }
    }

    float* ob = out + (long long)b * 65536 + blk_off(J) * 256 + blk_off(K);
#pragma unroll
    for (int nb = 0; nb < NBATCH; ++nb) {
        const int p0 = nb * PB;
        const int p1 = (p0 + PB < P) ? p0 + PB : P;
        __syncthreads();
#pragma unroll
        for (int a = 0; a < NPQ; ++a) {
            int pq = set * NPQ + a;
            if (pq < PQ) {
                int p = pq / Q;
                if (p >= p0 && p < p1) {
                    float4 v4;
                    v4.x = acc[a][0]; v4.y = acc[a][1];
                    v4.z = acc[a][2]; v4.w = acc[a][3];
                    ((float4*)sm)[(pq - p0 * Q) * 64 + lane] = v4;
                }
            }
        }
        __syncthreads();
        for (int idx = tid; idx < 64 * PQ; idx += 256) {
            int r_o = idx / (4 * Q);
            int c4 = idx - r_o * (4 * Q);
            int u = r_o / P;
            int p = r_o - u * P;
            if (p >= p0 && p < p1) {
                const float* bb = sm + (p - p0) * Q * 256 + u * 16;
                float4 o;
                { int c = 4 * c4 + 0; int v = c / Q; int q = c - v * Q; o.x = bb[q * 256 + v]; }
                { int c = 4 * c4 + 1; int v = c / Q; int q = c - v * Q; o.y = bb[q * 256 + v]; }
                { int c = 4 * c4 + 2; int v = c / Q; int q = c - v * Q; o.z = bb[q * 256 + v]; }
                { int c = 4 * c4 + 3; int v = c / Q; int q = c - v * Q; o.w = bb[q * 256 + v]; }
                *(float4*)(ob + r_o * 256 + 4 * c4) = o;
            }
        }
    }
}

__global__ void __launch_bounds__(256) phase2_all_kernel(float* __restrict__ out)
{
    __shared__ __align__(16) float sm[8960];
    switch (blockIdx.y) {
        case 0:  phase2_impl<0, 0>(out, sm); break;
        case 1:  phase2_impl<0, 1>(out, sm); break;
        case 2:  phase2_impl<0, 2>(out, sm); break;
        case 3:  phase2_impl<0, 3>(out, sm); break;
        case 4:  phase2_impl<1, 0>(out, sm); break;
        case 5:  phase2_impl<1, 1>(out, sm); break;
        case 6:  phase2_impl<1, 2>(out, sm); break;
        case 7:  phase2_impl<1, 3>(out, sm); break;
        case 8:  phase2_impl<2, 0>(out, sm); break;
        case 9:  phase2_impl<2, 1>(out, sm); break;
        case 10: phase2_impl<2, 2>(out, sm); break;
        case 11: phase2_impl<2, 3>(out, sm); break;
        case 12: phase2_impl<3, 0>(out, sm); break;
        case 13: phase2_impl<3, 1>(out, sm); break;
        case 14: phase2_impl<3, 2>(out, sm); break;
        default: phase2_impl<3, 3>(out, sm); break;
    }
}

// ============================================================================
extern "C" void kernel_launch(void* const* d_in, const int* in_sizes, int n_in,
                              void* d_out, int out_size)
{
    const float* x = (const float*)d_in[0];
    const float* w = (const float*)d_in[1];
    float* out = (float*)d_out;
    (void)in_sizes; (void)n_in; (void)out_size;

    const int DYN = 66560;
    cudaFuncSetAttribute(phase1_kernel<1>, cudaFuncAttributeMaxDynamicSharedMemorySize, DYN);
    cudaFuncSetAttribute(phase1_kernel<3>, cudaFuncAttributeMaxDynamicSharedMemorySize, DYN);
    cudaFuncSetAttribute(phase1_kernel<5>, cudaFuncAttributeMaxDynamicSharedMemorySize, DYN);
    cudaFuncSetAttribute(phase1_kernel<7>, cudaFuncAttributeMaxDynamicSharedMemorySize, DYN);
    cudaFuncSetAttribute(phase1_kernel<9>, cudaFuncAttributeMaxDynamicSharedMemorySize, DYN);

    // launch order chosen so ncu (-s 5 -c 1) captures phase1_kernel<9>
    wigner_init_kernel<<<40, 256>>>();                                        // 0
    prep_w_kernel<<<5120, 256>>>(w);                                          // 1
    prep_x_kernel<9><<<1024 * 9, 256>>>(x, xm_base_of(4), xoff_of(4));        // 2
    transpose_kernel<9><<<1024 * 9, 256>>>(x, xm_base_of(4), xoff_of(4));     // 3
    prep_x_kernel<7><<<1024 * 7, 256>>>(x, xm_base_of(3), xoff_of(3));        // 4
    phase1_kernel<9><<<dim3(16 * 9, 2 * ninstr_of(4)), 256, DYN>>>(           // 5
        w, group_first(4), group_first(4) * 32768,
        t_base_of(group_first(4)), xm_base_of(4), xm_base_of(4));
    transpose_kernel<7><<<1024 * 7, 256>>>(x, xm_base_of(3), xoff_of(3));
    phase1_kernel<7><<<dim3(16 * 7, 2 * ninstr_of(3)), 256, DYN>>>(
        w, group_first(3), group_first(3) * 32768,
        t_base_of(group_first(3)), xm_base_of(3), xm_base_of(3));
    prep_x_kernel<5><<<1024 * 5, 256>>>(x, xm_base_of(2), xoff_of(2));
    transpose_kernel<5><<<1024 * 5, 256>>>(x, xm_base_of(2), xoff_of(2));
    phase1_kernel<5><<<dim3(16 * 5, 2 * ninstr_of(2)), 256, DYN>>>(
        w, group_first(2), group_first(2) * 32768,
        t_base_of(group_first(2)), xm_base_of(2), xm_base_of(2));
    prep_x_kernel<3><<<1024 * 3, 256>>>(x, xm_base_of(1), xoff_of(1));
    transpose_kernel<3><<<1024 * 3, 256>>>(x, xm_base_of(1), xoff_of(1));
    phase1_kernel<3><<<dim3(16 * 3, 2 * ninstr_of(1)), 256, DYN>>>(
        w, group_first(1), group_first(1) * 32768,
        t_base_of(group_first(1)), xm_base_of(1), xm_base_of(1));
    prep_x_kernel<1><<<1024 * 1, 256>>>(x, xm_base_of(0), xoff_of(0));
    transpose_kernel<1><<<1024 * 1, 256>>>(x, xm_base_of(0), xoff_of(0));
    phase1_kernel<1><<<dim3(16 * 1, 2 * ninstr_of(0)), 256, DYN>>>(
        w, group_first(0), group_first(0) * 32768,
        t_base_of(group_first(0)), xm_base_of(0), xm_base_of(0));

    phase2_all_kernel<<<dim3(2048, 16), 256>>>(out);
}

// round 12
// speedup vs baseline: 1.6640x; 1.1633x over previous
#include <cuda_runtime.h>
#include <cuda_bf16.h>
#include <cstdint>

// ============================================================================
// Expansion (e3nn): MUL_IN=128, IN_LS=0..4, MUL_OUT=16, OUT_LS=0..3, B=2048.
//   init:    real Wigner-3j tables on device (fp64, exact reference formula)
//   prep:    bf16 hi/lo of x/128 (m-major) + W^T (n-major)
//   phase1:  ONE merged tcgen05 bf16-split GEMM kernel (runtime group decode)
//   phase2:  merged kernel, f32x2 inner loop, smem-staged coalesced stores
// ============================================================================

#if defined(__CUDA_ARCH_FEAT_SM103_ALL)
#define HAS_TC 1
#else
#define HAS_TC 0
#endif

#define DHC __host__ __device__ constexpr

DHC bool instr_valid(int i, int j, int k) {
    int d = j > k ? j - k : k - j;
    return d <= i && i <= j + k;
}
DHC int instr_id(int i, int j, int k) {
    int c = 0;
    for (int a = 0; a < 5; ++a)
        for (int b = 0; b < 4; ++b)
            for (int g = 0; g < 4; ++g)
                if (instr_valid(a, b, g)) {
                    if (a == i && b == j && g == k) return c;
                    ++c;
                }
    return -1;
}
DHC long long t_base_of(int id) {
    int c = 0; long long s = 0;
    for (int a = 0; a < 5; ++a)
        for (int b = 0; b < 4; ++b)
            for (int g = 0; g < 4; ++g)
                if (instr_valid(a, b, g)) {
                    if (c == id) return s * 524288LL;   // 2048*256
                    s += 2 * a + 1; ++c;
                }
    return 0;
}
DHC int w3j_off_of(int id) {
    int c = 0, s = 0;
    for (int a = 0; a < 5; ++a)
        for (int b = 0; b < 4; ++b)
            for (int g = 0; g < 4; ++g)
                if (instr_valid(a, b, g)) {
                    if (c == id) return s;
                    s += (2 * b + 1) * (2 * g + 1) * (2 * a + 1); ++c;
                }
    return 0;
}
DHC int blk_off(int l) { return l == 0 ? 0 : l == 1 ? 16 : l == 2 ? 64 : 144; }
DHC int sum_L(int J, int K) {
    int s = 0;
    for (int i = 0; i < 5; ++i) if (instr_valid(i, J, K)) s += 2 * i + 1;
    return s;
}
DHC int xoff_of(int i) { int s = 0; for (int l = 0; l < i; ++l) s += 2 * l + 1; return 128 * s; }
DHC int ninstr_of(int i) {
    int c = 0;
    for (int b = 0; b < 4; ++b) for (int g = 0; g < 4; ++g) if (instr_valid(i, b, g)) ++c;
    return c;
}
DHC int group_first(int i) {
    for (int b = 0; b < 4; ++b) for (int g = 0; g < 4; ++g)
        if (instr_valid(i, b, g)) return instr_id(i, b, g);
    return 0;
}
DHC long long xm_base_of(int i) {
    long long s = 0;
    for (int l = 0; l < i; ++l) s += 2 * l + 1;
    return 262144LL * s;            // 2048*128 * sum(2l+1)
}
DHC int p1_cnt_of(int i) { return 16 * (2 * i + 1) * 2 * ninstr_of(i); }

// ---------------- device scratch ----------------
__device__ float g_t[110100480];                         // 440 MB
__device__ __align__(16) __nv_bfloat16 g_xh[6553600];    // (x/128) hi, [group][m][k]
__device__ __align__(16) __nv_bfloat16 g_xl[6553600];    // (x/128) lo
__device__ __align__(16) __nv_bfloat16 g_wh[1310720];    // W^T hi, [instr][n][k]
__device__ __align__(16) __nv_bfloat16 g_wl[1310720];    // W^T lo
__device__ float g_w3j[5110];

// ---------------- f32x2 helpers (base ISA, both targets) ----------------
__device__ __forceinline__ unsigned long long pack2(float lo, float hi) {
    unsigned long long r;
    asm("mov.b64 %0, {%1, %2};" : "=l"(r) : "r"(__float_as_uint(lo)), "r"(__float_as_uint(hi)));
    return r;
}
#define FMA2(acc, a, b) asm("fma.rn.f32x2 %0, %1, %2, %0;" : "+l"(acc) : "l"(a), "l"(b))

// ============================================================================
// sm_103a-only helpers
// ============================================================================
__device__ __forceinline__ uint32_t smem_u32(const void* p) {
    uint32_t a;
    asm("{ .reg .u64 t; cvta.to.shared.u64 t, %1; cvt.u32.u64 %0, t; }" : "=r"(a) : "l"(p));
    return a;
}
__device__ __forceinline__ uint32_t elect_one_pred() {
#if HAS_TC
    uint32_t pred;
    asm volatile(
        "{\n\t.reg .pred p;\n\telect.sync _|p, 0xFFFFFFFF;\n\tselp.b32 %0, 1, 0, p;\n\t}"
        : "=r"(pred));
    return pred;
#else
    return (threadIdx.x & 31) == 0;
#endif
}
#if HAS_TC
#define TCGEN05_ALLOC(smem_addr, nCols) \
    asm volatile("tcgen05.alloc.cta_group::1.sync.aligned.shared::cta.b32 [%0], %1;" \
                 :: "r"((uint32_t)(smem_addr)), "r"((uint32_t)(nCols)) : "memory")
#define TCGEN05_DEALLOC(tmem_addr, nCols) \
    asm volatile("tcgen05.dealloc.cta_group::1.sync.aligned.b32 %0, %1;" \
                 :: "r"(tmem_addr), "r"((uint32_t)(nCols)))
#define TCGEN05_WAIT_ST() asm volatile("tcgen05.wait::st.sync.aligned;" ::: "memory")
#define TCGEN05_WAIT_LD() asm volatile("tcgen05.wait::ld.sync.aligned;" ::: "memory")
#define TCGEN05_FENCE_BEFORE() asm volatile("tcgen05.fence::before_thread_sync;" ::: "memory")
#define TCGEN05_FENCE_AFTER()  asm volatile("tcgen05.fence::after_thread_sync;" ::: "memory")
#define TCGEN05_COMMIT(mbar) \
    asm volatile("tcgen05.commit.cta_group::1.mbarrier::arrive::one.shared::cluster.b64 [%0];" \
                 :: "r"((uint32_t)(mbar)) : "memory")
#define MBARRIER_INIT(mbar, count) \
    asm volatile("mbarrier.init.shared.b64 [%0], %1;" \
                 :: "r"((uint32_t)(mbar)), "r"((uint32_t)(count)) : "memory")
#define MBARRIER_INVAL(mbar) \
    asm volatile("mbarrier.inval.shared.b64 [%0];" :: "r"((uint32_t)(mbar)) : "memory")
#define MBARRIER_WAIT_PARITY(mbar_smem_addr, phase_parity) do { \
    uint32_t _mbar = (uint32_t)(mbar_smem_addr); \
    uint32_t _parity = (uint32_t)(phase_parity); \
    uint32_t _done; \
    asm volatile( \
        "{\n\t.reg .pred p;\n\t" \
        "mbarrier.try_wait.parity.acquire.cta.shared::cta.b64 p, [%1], %2;\n\t" \
        "selp.b32 %0, 1, 0, p;\n\t}" \
        : "=r"(_done) : "r"(_mbar), "r"(_parity) : "memory"); \
    if (!_done) { \
        asm volatile( \
            "{\n\t.reg .pred P1;\n\t" \
            "WAIT_LOOP_%=:\n\t" \
            "mbarrier.try_wait.parity.acquire.cta.shared::cta.b64 P1, [%0], %1, 0x989680;\n\t" \
            "@P1 bra.uni WAIT_DONE_%=;\n\t" \
            "bra.uni WAIT_LOOP_%=;\n\t" \
            "WAIT_DONE_%=:\n\t}" \
            :: "r"(_mbar), "r"(_parity) : "memory"); \
    } \
} while (0)
#define TCGEN05_MMA_F16(d_tmem, a_tmem, b_smem_desc, idesc, enable_d) do { \
    uint32_t _enable = (enable_d) ? 1 : 0; \
    uint32_t _zero = 0; \
    asm volatile( \
        "{\n\t.reg .pred p;\n\tsetp.ne.u32 p, %6, 0;\n\t" \
        "tcgen05.mma.cta_group::1.kind::f16 [%0], [%1], %2, %3, " \
        "{%4, %4, %4, %4}, p;\n\t}" \
        :: "r"(d_tmem), "r"(a_tmem), "l"(b_smem_desc), "r"(idesc), \
           "r"(_zero), "r"(_zero), "r"(_enable) \
        : "memory"); \
} while (0)
#define TCGEN05_LD_32X32B_X32(r, tmem_addr) \
    asm volatile( \
        "tcgen05.ld.sync.aligned.32x32b.x32.b32 " \
        "{%0, %1, %2, %3, %4, %5, %6, %7, " \
        " %8, %9, %10, %11, %12, %13, %14, %15, " \
        " %16, %17, %18, %19, %20, %21, %22, %23, " \
        " %24, %25, %26, %27, %28, %29, %30, %31}, [%32];" \
        : "=r"((r)[0]),  "=r"((r)[1]),  "=r"((r)[2]),  "=r"((r)[3]), \
          "=r"((r)[4]),  "=r"((r)[5]),  "=r"((r)[6]),  "=r"((r)[7]), \
          "=r"((r)[8]),  "=r"((r)[9]),  "=r"((r)[10]), "=r"((r)[11]), \
          "=r"((r)[12]), "=r"((r)[13]), "=r"((r)[14]), "=r"((r)[15]), \
          "=r"((r)[16]), "=r"((r)[17]), "=r"((r)[18]), "=r"((r)[19]), \
          "=r"((r)[20]), "=r"((r)[21]), "=r"((r)[22]), "=r"((r)[23]), \
          "=r"((r)[24]), "=r"((r)[25]), "=r"((r)[26]), "=r"((r)[27]), \
          "=r"((r)[28]), "=r"((r)[29]), "=r"((r)[30]), "=r"((r)[31]) \
        : "r"(tmem_addr))
#define TCGEN05_ST_32X32B_X64(tmem_addr, r) \
    asm volatile( \
        "tcgen05.st.sync.aligned.32x32b.x64.b32 [%0], " \
        "{%1, %2, %3, %4, %5, %6, %7, %8, " \
        " %9, %10, %11, %12, %13, %14, %15, %16, " \
        " %17, %18, %19, %20, %21, %22, %23, %24, " \
        " %25, %26, %27, %28, %29, %30, %31, %32, " \
        " %33, %34, %35, %36, %37, %38, %39, %40, " \
        " %41, %42, %43, %44, %45, %46, %47, %48, " \
        " %49, %50, %51, %52, %53, %54, %55, %56, " \
        " %57, %58, %59, %60, %61, %62, %63, %64};" \
        :: "r"(tmem_addr), \
           "r"((r)[0]),  "r"((r)[1]),  "r"((r)[2]),  "r"((r)[3]), \
           "r"((r)[4]),  "r"((r)[5]),  "r"((r)[6]),  "r"((r)[7]), \
           "r"((r)[8]),  "r"((r)[9]),  "r"((r)[10]), "r"((r)[11]), \
           "r"((r)[12]), "r"((r)[13]), "r"((r)[14]), "r"((r)[15]), \
           "r"((r)[16]), "r"((r)[17]), "r"((r)[18]), "r"((r)[19]), \
           "r"((r)[20]), "r"((r)[21]), "r"((r)[22]), "r"((r)[23]), \
           "r"((r)[24]), "r"((r)[25]), "r"((r)[26]), "r"((r)[27]), \
           "r"((r)[28]), "r"((r)[29]), "r"((r)[30]), "r"((r)[31]), \
           "r"((r)[32]), "r"((r)[33]), "r"((r)[34]), "r"((r)[35]), \
           "r"((r)[36]), "r"((r)[37]), "r"((r)[38]), "r"((r)[39]), \
           "r"((r)[40]), "r"((r)[41]), "r"((r)[42]), "r"((r)[43]), \
           "r"((r)[44]), "r"((r)[45]), "r"((r)[46]), "r"((r)[47]), \
           "r"((r)[48]), "r"((r)[49]), "r"((r)[50]), "r"((r)[51]), \
           "r"((r)[52]), "r"((r)[53]), "r"((r)[54]), "r"((r)[55]), \
           "r"((r)[56]), "r"((r)[57]), "r"((r)[58]), "r"((r)[59]), \
           "r"((r)[60]), "r"((r)[61]), "r"((r)[62]), "r"((r)[63]) \
        : "memory")
#endif  // HAS_TC
static constexpr unsigned long long SMEM_DESC_BASE_SW128 =
    (2ULL << 61) | (1ULL << 46) | (64ULL << 32) | (1ULL << 16);
#define MAKE_SMEM_DESC(base_addr) \
    (SMEM_DESC_BASE_SW128 | ((unsigned long long)((base_addr) >> 4) & 0x3FFF))
#define SMEM_SWIZZLE_128B(o) ((o) ^ (((o) >> 3) & 0x70))

// idesc kind::f16: F32 accum, BF16 a/b, N=128, M=128
static constexpr uint32_t IDESC_BF16_M128_N128 =
    (1u << 4) | (1u << 7) | (1u << 10) | (16u << 17) | (8u << 24);

// ============================================================================
// Wigner-3j init (fp64)
// ============================================================================
struct cd { double re, im; };
__device__ __forceinline__ cd cmul(cd a, cd b) {
    cd r; r.re = a.re * b.re - a.im * b.im; r.im = a.re * b.im + a.im * b.re; return r;
}
__device__ const double g_fact[13] = {
    1.0, 1.0, 2.0, 6.0, 24.0, 120.0, 720.0, 5040.0, 40320.0, 362880.0,
    3628800.0, 39916800.0, 479001600.0
};
__device__ double su2cg(int j1, int m1, int j2, int m2, int j3, int m3) {
    const double* F = g_fact;
    double C = sqrt((2.0 * j3 + 1.0) * F[j3 + j1 - j2] * F[j3 - j1 + j2] * F[j1 + j2 - j3]
                    * F[j3 + m3] * F[j3 - m3]
                    / (F[j1 + j2 + j3 + 1] * F[j1 - m1] * F[j1 + m1] * F[j2 - m2] * F[j2 + m2]));
    int vmin = -j1 + j2 + m3; if (-j1 + m1 > vmin) vmin = -j1 + m1; if (vmin < 0) vmin = 0;
    int vmax = j2 + j3 + m1;
    if (j3 - j1 + j2 < vmax) vmax = j3 - j1 + j2;
    if (j3 + m3 < vmax) vmax = j3 + m3;
    double S = 0.0;
    for (int v = vmin; v <= vmax; ++v) {
        double sgn = ((v + j2 + m2) & 1) ? -1.0 : 1.0;
        S += sgn * F[j2 + j3 + m1 - v] * F[j1 - m1 + v]
             / (F[v] * F[j3 - j1 + j2 - v] * F[j3 + m3 - v] * F[v + j1 - j2 - m3]);
    }
    return C * S;
}
__device__ cd q_ent(int l, int r, int c) {
    const double s = 0.70710678118654752440;
    int m = r - l;
    cd v; v.re = 0.0; v.im = 0.0;
    if (m < 0) {
        if (c == l - m)      { v.re = s; }
        else if (c == l + m) { v.im = -s; }
    } else if (m == 0) {
        if (c == l) v.re = 1.0;
    } else {
        double sg = (m & 1) ? -1.0 : 1.0;
        if (c == l + m)      { v.re = sg * s; }
        else if (c == l - m) { v.im = sg * s; }
    }
    int ph = l & 3;
    cd o = v;
    if (ph == 1)      { o.re = v.im;  o.im = -v.re; }
    else if (ph == 2) { o.re = -v.re; o.im = -v.im; }
    else if (ph == 3) { o.re = -v.im; o.im = v.re; }
    return o;
}
__global__ void __launch_bounds__(256) wigner_init_kernel() {
    __shared__ double vals[1225];
    __shared__ double red[256];
    const int tid = threadIdx.x;
    const int id = blockIdx.x;
    int l1 = 0, l2 = 0, l3 = 0;
    {
        int c = 0;
        for (int a = 0; a < 5; ++a)
            for (int bb = 0; bb < 4; ++bb)
                for (int g = 0; g < 4; ++g)
                    if (instr_valid(a, bb, g)) {
                        if (c == id) { l3 = a; l1 = bb; l2 = g; }
                        ++c;
                    }
    }
    const int P = 2 * l1 + 1, Q2 = 2 * l2 + 1, R = 2 * l3 + 1;
    const int n = P * Q2 * R;
    double ss = 0.0;
    for (int e = tid; e < n; e += 256) {
        int jj = e / (Q2 * R);
        int rem = e - jj * (Q2 * R);
        int ll = rem / R;
        int mm = rem - ll * R;
        cd s; s.re = 0.0; s.im = 0.0;
        for (int i1 = 0; i1 < P; ++i1) {
            cd q1 = q_ent(l1, i1, jj);
            if (q1.re == 0.0 && q1.im == 0.0) continue;
            int m1 = i1 - l1;
            for (int k1 = 0; k1 < Q2; ++k1) {
                int m2 = k1 - l2;
                int m3 = m1 + m2;
                if (m3 < -l3 || m3 > l3) continue;
                cd q2 = q_ent(l2, k1, ll);
                if (q2.re == 0.0 && q2.im == 0.0) continue;
                cd q3 = q_ent(l3, l3 + m3, mm);
                if (q3.re == 0.0 && q3.im == 0.0) continue;
                double cg = su2cg(l1, m1, l2, m2, l3, m3);
                if (cg == 0.0) continue;
                cd q3c; q3c.re = q3.re; q3c.im = -q3.im;
                cd t = cmul(cmul(q1, q2), q3c);
                s.re += cg * t.re;
                s.im += cg * t.im;
            }
        }
        vals[e] = s.re;
        ss += s.re * s.re;
    }
    red[tid] = ss;
    __syncthreads();
    for (int st = 128; st > 0; st >>= 1) {
        if (tid < st) red[tid] += red[tid + st];
        __syncthreads();
    }
    const double inv = 1.0 / sqrt(red[0]);
    const int wo = w3j_off_of(id);
    for (int e = tid; e < n; e += 256)
        g_w3j[wo + e] = (float)(vals[e] * inv);
}

// ============================================================================
// Prep kernels (scale 1/128 folded into x split)
// ============================================================================
__global__ void __launch_bounds__(256) prep_x_all_kernel(
    const float* __restrict__ x, long long start)
{
    long long idx = start + (long long)blockIdx.x * 256 + threadIdx.x;
    long long t = idx >> 18;                     // units of 262144
    int gi = (t < 1) ? 0 : (t < 4) ? 1 : (t < 9) ? 2 : (t < 16) ? 3 : 4;
    long long local = idx - xm_base_of(gi);
    int L = 2 * gi + 1;
    int m = (int)(local >> 7);
    int kk = (int)(local & 127);
    int b = m / L, r = m - b * L;
    float v = x[b * 3200 + xoff_of(gi) + kk * L + r] * 0.0078125f;
    __nv_bfloat16 hi = __float2bfloat16_rn(v);
    __nv_bfloat16 lo = __float2bfloat16_rn(v - __bfloat162float(hi));
    g_xh[idx] = hi;
    g_xl[idx] = lo;
}
__global__ void __launch_bounds__(256) prep_w_kernel(const float* __restrict__ w)
{
    int idx = blockIdx.x * 256 + threadIdx.x;   // 40*32768 exact
    int instr = idx >> 15;
    int rem = idx & 32767;
    int n = rem >> 7, k = rem & 127;
    float v = w[instr * 32768 + k * 256 + n];
    __nv_bfloat16 hi = __float2bfloat16_rn(v);
    __nv_bfloat16 lo = __float2bfloat16_rn(v - __bfloat162float(hi));
    g_wh[idx] = hi;
    g_wl[idx] = lo;
}

// ============================================================================
// Phase 1 (merged, runtime decode). grid 6720, block 256, dyn smem 66560.
// ============================================================================
__global__ void __launch_bounds__(256, 2)
#if HAS_TC
__cluster_dims__(1, 1, 1)
#endif
phase1_all_kernel(const float* __restrict__ wflat)
{
    extern __shared__ __align__(16) char dyn[];
    const int tid = threadIdx.x;

    // decode blockIdx.x -> (group gi, il, nt, m0)
    int rem = blockIdx.x;
    int gi = 0;
#pragma unroll
    for (int i = 0; i < 4; ++i) {
        int n = p1_cnt_of(i);
        if (rem >= n && gi == i) { rem -= n; gi = i + 1; }
    }
    const int L = 2 * gi + 1;
    const int W16L = 16 * L;
    const int il_nt = rem / W16L;
    const int m0 = (rem - il_nt * W16L) * 128;
    const int il = il_nt >> 1;
    const int nt = il_nt & 1;
    const int instr = group_first(gi) + il;
    const long long xbase = xm_base_of(gi);
    float* tC_base = g_t + t_base_of(group_first(gi)) + (long long)il * (2048LL * L * 256);

#if HAS_TC
    // ------------------------------------------------------------- tensor path
    __shared__ uint32_t s_tmem;
    __shared__ __align__(8) unsigned long long s_mbar;
    const int wid = tid >> 5, lid = tid & 31;

    const uint32_t dynb = smem_u32(dyn);
    const uint32_t bh = (dynb + 1023u) & ~1023u;
    const uint32_t bl = bh + 32768u;
    char* p_bh = dyn + (bh - dynb);
    char* p_bl = dyn + (bl - dynb);

    if (wid == 0) TCGEN05_ALLOC(smem_u32(&s_tmem), 256);
    if (tid == 0) MBARRIER_INIT(smem_u32(&s_mbar), 1);
    __syncthreads();
    const uint32_t tmem = s_tmem;     // D: 0..127, A_hi: 128..191, A_lo: 192..255
    const uint32_t mbar = smem_u32(&s_mbar);

    if (tid < 128) {
        const uint32_t warp_off = ((uint32_t)wid) << 21;
        uint32_t a[64];
        const uint4* src = (const uint4*)(g_xh + xbase + (long long)(m0 + tid) * 128);
#pragma unroll
        for (int i = 0; i < 16; ++i) {
            uint4 v = src[i];
            a[i * 4 + 0] = v.x; a[i * 4 + 1] = v.y; a[i * 4 + 2] = v.z; a[i * 4 + 3] = v.w;
        }
        TCGEN05_ST_32X32B_X64(tmem + 128 + warp_off, a);
        TCGEN05_WAIT_ST();
        const uint4* src2 = (const uint4*)(g_xl + xbase + (long long)(m0 + tid) * 128);
#pragma unroll
        for (int i = 0; i < 16; ++i) {
            uint4 v = src2[i];
            a[i * 4 + 0] = v.x; a[i * 4 + 1] = v.y; a[i * 4 + 2] = v.z; a[i * 4 + 3] = v.w;
        }
        TCGEN05_ST_32X32B_X64(tmem + 192 + warp_off, a);
        TCGEN05_WAIT_ST();
    }

    {
        const uint4* srch = (const uint4*)(g_wh + (long long)instr * 32768 + nt * 16384);
        const uint4* srcl = (const uint4*)(g_wl + (long long)instr * 32768 + nt * 16384);
#pragma unroll
        for (int it = 0; it < 8; ++it) {
            int idx = tid + it * 256;            // n*16 + c
            int n = idx >> 4, c = idx & 15;
            uint32_t byte_off = (uint32_t)(((n >> 3) + (c >> 3) * 16) * 1024
                                           + (n & 7) * 128 + (c & 7) * 16);
            uint32_t sw = SMEM_SWIZZLE_128B(byte_off);
            *(uint4*)(p_bh + sw) = srch[idx];
            *(uint4*)(p_bl + sw) = srcl[idx];
        }
    }
    TCGEN05_FENCE_BEFORE();
    __syncthreads();

    if (wid == 0) {
        TCGEN05_FENCE_AFTER();
        const unsigned long long bdh = MAKE_SMEM_DESC(bh);
        const unsigned long long bdl = MAKE_SMEM_DESC(bl);
        const uint32_t offs[8] = {0, 2, 4, 6, 1024, 1026, 1028, 1030};
        if (elect_one_pred()) {
#pragma unroll
            for (int k = 0; k < 8; ++k)
                TCGEN05_MMA_F16(tmem, tmem + 128 + k * 8, bdh + offs[k],
                                IDESC_BF16_M128_N128, k > 0);
#pragma unroll
            for (int k = 0; k < 8; ++k)
                TCGEN05_MMA_F16(tmem, tmem + 192 + k * 8, bdh + offs[k],
                                IDESC_BF16_M128_N128, true);
#pragma unroll
            for (int k = 0; k < 8; ++k)
                TCGEN05_MMA_F16(tmem, tmem + 128 + k * 8, bdl + offs[k],
                                IDESC_BF16_M128_N128, true);
            TCGEN05_COMMIT(mbar);
        }
    }
    __syncthreads();
    MBARRIER_WAIT_PARITY(mbar, 0);
    TCGEN05_FENCE_AFTER();

    if (tid < 128) {
        float* tC = tC_base + (long long)(m0 + wid * 32 + lid) * 256 + nt * 128;
#pragma unroll
        for (int c4 = 0; c4 < 4; ++c4) {
            uint32_t r[32];
            TCGEN05_LD_32X32B_X32(r, tmem + c4 * 32);
            TCGEN05_WAIT_LD();
#pragma unroll
            for (int j = 0; j < 8; ++j) {
                float4 o;
                o.x = __uint_as_float(r[j * 4 + 0]);
                o.y = __uint_as_float(r[j * 4 + 1]);
                o.z = __uint_as_float(r[j * 4 + 2]);
                o.w = __uint_as_float(r[j * 4 + 3]);
                *(float4*)(tC + c4 * 32 + j * 4) = o;
            }
        }
        TCGEN05_FENCE_BEFORE();
    }
    __syncthreads();
    if (tid == 0) MBARRIER_INVAL(mbar);
    if (wid == 0) TCGEN05_DEALLOC(tmem, 256);

#else
    // -------------------------------------------- FFMA fallback (never runs
    // when sm_103a SASS is loaded; present so the compute_103 pass compiles
    // and stays correct if PTX-JIT were ever used)
    float* As = (float*)dyn;                     // [32][128]
    float* Bs = (float*)(dyn + 16384);           // [32][128]
    const int uv0 = nt * 128;
    const float* wB = wflat + (long long)instr * 32768 + uv0;
    const int ty = tid >> 4, tx = tid & 15;

    unsigned long long acc2[8][4];
#pragma unroll
    for (int u = 0; u < 8; ++u)
#pragma unroll
        for (int v = 0; v < 4; ++v) acc2[u][v] = 0ULL;

    for (int k0 = 0; k0 < 128; k0 += 32) {
#pragma unroll
        for (int it = 0; it < 16; ++it) {
            int e = tid + 256 * it;
            int ml = e & 127, kk = e >> 7;
            long long off = xbase + (long long)(m0 + ml) * 128 + (k0 + kk);
            As[kk * 128 + ml] = __bfloat162float(g_xh[off]) + __bfloat162float(g_xl[off]);
        }
#pragma unroll
        for (int it = 0; it < 16; ++it) {
            int e = tid + 256 * it;
            int nl = e & 127, kk = e >> 7;
            Bs[kk * 128 + nl] = wB[(k0 + kk) * 256 + nl];
        }
        __syncthreads();
#pragma unroll
        for (int kk = 0; kk < 32; ++kk) {
            float4 a0 = *(const float4*)(&As[kk * 128 + ty * 8]);
            float4 a1 = *(const float4*)(&As[kk * 128 + ty * 8 + 4]);
            ulonglong2 b01 = *(const ulonglong2*)(&Bs[kk * 128 + tx * 8]);
            ulonglong2 b23 = *(const ulonglong2*)(&Bs[kk * 128 + tx * 8 + 4]);
            unsigned long long bp[4] = { b01.x, b01.y, b23.x, b23.y };
            float av[8] = { a0.x, a0.y, a0.z, a0.w, a1.x, a1.y, a1.z, a1.w };
#pragma unroll
            for (int u = 0; u < 8; ++u) {
                unsigned long long ad = pack2(av[u], av[u]);
                FMA2(acc2[u][0], ad, bp[0]);
                FMA2(acc2[u][1], ad, bp[1]);
                FMA2(acc2[u][2], ad, bp[2]);
                FMA2(acc2[u][3], ad, bp[3]);
            }
        }
        __syncthreads();
    }
#pragma unroll
    for (int u = 0; u < 8; ++u) {
        int m = m0 + ty * 8 + u;
        float2 p0 = *(float2*)&acc2[u][0];
        float2 p1 = *(float2*)&acc2[u][1];
        float2 p2 = *(float2*)&acc2[u][2];
        float2 p3 = *(float2*)&acc2[u][3];
        float4 o0, o1;
        o0.x = p0.x; o0.y = p0.y; o0.z = p1.x; o0.w = p1.y;
        o1.x = p2.x; o1.y = p2.y; o1.z = p3.x; o1.w = p3.y;
        float* dst = tC_base + (long long)m * 256 + uv0 + tx * 8;
        *(float4*)dst = o0;
        *(float4*)(dst + 4) = o1;
    }
#endif
}

// ============================================================================
// Phase 2 (merged, f32x2 inner loop)
// ============================================================================
template<int J, int K>
__device__ __forceinline__ void phase2_impl(float* __restrict__ out, float* sm)
{
    constexpr int P = 2 * J + 1, Q = 2 * K + 1, PQ = P * Q;
    constexpr int SUML = sum_L(J, K);
    constexpr int NPQ = (PQ + 3) / 4;
    constexpr int PB = (PQ * 1024 > 40000) ? (P + 1) / 2 : P;
    constexpr int NBATCH = (P + PB - 1) / PB;
    float* ts = sm;
    unsigned long long* ws2 = (unsigned long long*)(sm + SUML * 256);  // duplicated f32x2
    const int tid = threadIdx.x;
    const int b = blockIdx.x;

    int kb = 0;
#pragma unroll
    for (int i = 0; i < 5; ++i) {
        if (!instr_valid(i, J, K)) continue;
        const int Ri = 2 * i + 1;
        const int id = instr_id(i, J, K);
        const long long tb = t_base_of(id) + (long long)b * (Ri * 256);
        const float4* src = (const float4*)(g_t + tb);
        float4* dst = (float4*)(ts + kb * 256);
        for (int idx = tid; idx < Ri * 64; idx += 256) dst[idx] = src[idx];
        const int wo = w3j_off_of(id);
        for (int idx = tid; idx < PQ * Ri; idx += 256) {
            int pq = idx / Ri, r = idx - pq * Ri;
            float wv = g_w3j[wo + idx];
            ws2[(kb + r) * PQ + pq] = pack2(wv, wv);
        }
        kb += Ri;
    }
    __syncthreads();

    const int lane = tid & 63;
    const int set = tid >> 6;

    unsigned long long acc2[NPQ][2];
#pragma unroll
    for (int a = 0; a < NPQ; ++a) { acc2[a][0] = 0ULL; acc2[a][1] = 0ULL; }

#pragma unroll
    for (int kk = 0; kk < SUML; ++kk) {
        ulonglong2 t2 = *(const ulonglong2*)(ts + kk * 256 + lane * 4);
#pragma unroll
        for (int a = 0; a < NPQ; ++a) {
            int pq = set * NPQ + a;
            if (pq >= PQ) pq = PQ - 1;
            unsigned long long w2 = ws2[kk * PQ + pq];   // warp-uniform broadcast
            FMA2(acc2[a][0], w2, t2.x);
            FMA2(acc2[a][1], w2, t2.y);
        }
    }

    float* ob = out + (long long)b * 65536 + blk_off(J) * 256 + blk_off(K);
#pragma unroll
    for (int nb = 0; nb < NBATCH; ++nb) {
        const int p0 = nb * PB;
        const int p1 = (p0 + PB < P) ? p0 + PB : P;
        __syncthreads();
#pragma unroll
        for (int a = 0; a < NPQ; ++a) {
            int pq = set * NPQ + a;
            if (pq < PQ) {
                int p = pq / Q;
                if (p >= p0 && p < p1) {
                    float2 xy = *(float2*)&acc2[a][0];
                    float2 zw = *(float2*)&acc2[a][1];
                    float4 v4;
                    v4.x = xy.x; v4.y = xy.y; v4.z = zw.x; v4.w = zw.y;
                    ((float4*)sm)[(pq - p0 * Q) * 64 + lane] = v4;
                }
            }
        }
        __syncthreads();
        for (int idx = tid; idx < 64 * PQ; idx += 256) {
            int r_o = idx / (4 * Q);
            int c4 = idx - r_o * (4 * Q);
            int u = r_o / P;
            int p = r_o - u * P;
            if (p >= p0 && p < p1) {
                const float* bb = sm + (p - p0) * Q * 256 + u * 16;
                float4 o;
                { int c = 4 * c4 + 0; int v = c / Q; int q = c - v * Q; o.x = bb[q * 256 + v]; }
                { int c = 4 * c4 + 1; int v = c / Q; int q = c - v * Q; o.y = bb[q * 256 + v]; }
                { int c = 4 * c4 + 2; int v = c / Q; int q = c - v * Q; o.z = bb[q * 256 + v]; }
                { int c = 4 * c4 + 3; int v = c / Q; int q = c - v * Q; o.w = bb[q * 256 + v]; }
                *(float4*)(ob + r_o * 256 + 4 * c4) = o;
            }
        }
    }
}

__global__ void __launch_bounds__(256) phase2_all_kernel(float* __restrict__ out)
{
    __shared__ __align__(16) float sm[8960];
    switch (blockIdx.y) {
        case 0:  phase2_impl<0, 0>(out, sm); break;
        case 1:  phase2_impl<0, 1>(out, sm); break;
        case 2:  phase2_impl<0, 2>(out, sm); break;
        case 3:  phase2_impl<0, 3>(out, sm); break;
        case 4:  phase2_impl<1, 0>(out, sm); break;
        case 5:  phase2_impl<1, 1>(out, sm); break;
        case 6:  phase2_impl<1, 2>(out, sm); break;
        case 7:  phase2_impl<1, 3>(out, sm); break;
        case 8:  phase2_impl<2, 0>(out, sm); break;
        case 9:  phase2_impl<2, 1>(out, sm); break;
        case 10: phase2_impl<2, 2>(out, sm); break;
        case 11: phase2_impl<2, 3>(out, sm); break;
        case 12: phase2_impl<3, 0>(out, sm); break;
        case 13: phase2_impl<3, 1>(out, sm); break;
        case 14: phase2_impl<3, 2>(out, sm); break;
        default: phase2_impl<3, 3>(out, sm); break;
    }
}

// ============================================================================
extern "C" void kernel_launch(void* const* d_in, const int* in_sizes, int n_in,
                              void* d_out, int out_size)
{
    const float* x = (const float*)d_in[0];
    const float* w = (const float*)d_in[1];
    float* out = (float*)d_out;
    (void)in_sizes; (void)n_in; (void)out_size;

    const int DYN = 66560;
    cudaFuncSetAttribute(phase1_all_kernel, cudaFuncAttributeMaxDynamicSharedMemorySize, DYN);

    wigner_init_kernel<<<40, 256>>>();                       // 0
    prep_w_kernel<<<5120, 256>>>(w);                         // 1
    prep_x_all_kernel<<<16384, 256>>>(x, 0LL);               // 2  groups 0..3
    prep_x_all_kernel<<<9216, 256>>>(x, 4194304LL);          // 3  group 4
    phase1_all_kernel<<<6720, 256, DYN>>>(w);                // 4
    phase2_all_kernel<<<dim3(2048, 16), 256>>>(out);         // 5  <- ncu capture
}